// round 1
// baseline (speedup 1.0000x reference)
#include <cuda_runtime.h>

#define B_   2
#define S_   2048
#define H_   16
#define D_   64
#define HID_ 1024
#define ROT_ 32
#define BS_  (B_*S_)

// Scratch (allocation-free rule: __device__ globals)
__device__ float g_q[(size_t)B_*H_*S_*D_];
__device__ float g_k[(size_t)B_*H_*S_*D_];
__device__ float g_v[(size_t)B_*H_*S_*D_];
__device__ float g_attn[(size_t)BS_*HID_];

// ---------------------------------------------------------------------------
// Kernel 1: fused QKV GEMM.  C[4096 x 3072] = x @ [Wq|Wk|Wv] + bias, with
// rope-scale fused into epilogue for q/k, and q *= 1/sqrt(D).
// Writes q,k,v in [B,H,S,D] layout for the attention kernel.
// Tile: 128x128, BK=16, 256 threads, 8x8 per-thread microtile.
// ---------------------------------------------------------------------------
__global__ __launch_bounds__(256) void qkv_kernel(
    const float* __restrict__ x, const float* __restrict__ sinu,
    const float* __restrict__ Wq, const float* __restrict__ bq,
    const float* __restrict__ Wk, const float* __restrict__ bk,
    const float* __restrict__ Wv, const float* __restrict__ bv)
{
    const int bn  = blockIdx.x * 128;           // 0..3071 (3 matrices concatenated)
    const int bm  = blockIdx.y * 128;           // 0..4095
    const int mat = bn >> 10;                   // 0=q, 1=k, 2=v
    const float* __restrict__ W    = (mat == 0) ? Wq : (mat == 1) ? Wk : Wv;
    const float* __restrict__ bvec = (mat == 0) ? bq : (mat == 1) ? bk : bv;
    const int n0 = bn & (HID_ - 1);

    __shared__ float As[16][132];   // padded: transpose-store conflicts reduced
    __shared__ float Bs[16][128];

    const int tid  = threadIdx.x;
    const int tx   = tid & 15;
    const int ty   = tid >> 4;
    const int arow = tid >> 2;              // 0..63
    const int acol = (tid & 3) << 2;        // 0,4,8,12
    const int brow = tid >> 5;              // 0..7
    const int bcol = (tid & 31) << 2;       // 0..124

    float acc[8][8];
    #pragma unroll
    for (int i = 0; i < 8; i++)
        #pragma unroll
        for (int j = 0; j < 8; j++) acc[i][j] = 0.0f;

    for (int kt = 0; kt < HID_; kt += 16) {
        float4 a0 = *(const float4*)&x[(size_t)(bm + arow)      * HID_ + kt + acol];
        float4 a1 = *(const float4*)&x[(size_t)(bm + arow + 64) * HID_ + kt + acol];
        float4 w0 = *(const float4*)&W[(size_t)(kt + brow)      * HID_ + n0 + bcol];
        float4 w1 = *(const float4*)&W[(size_t)(kt + brow + 8)  * HID_ + n0 + bcol];

        __syncthreads();
        As[acol + 0][arow]      = a0.x;
        As[acol + 1][arow]      = a0.y;
        As[acol + 2][arow]      = a0.z;
        As[acol + 3][arow]      = a0.w;
        As[acol + 0][arow + 64] = a1.x;
        As[acol + 1][arow + 64] = a1.y;
        As[acol + 2][arow + 64] = a1.z;
        As[acol + 3][arow + 64] = a1.w;
        *(float4*)&Bs[brow][bcol]     = w0;
        *(float4*)&Bs[brow + 8][bcol] = w1;
        __syncthreads();

        #pragma unroll
        for (int kk = 0; kk < 16; kk++) {
            float a[8], b[8];
            *(float4*)&a[0] = *(const float4*)&As[kk][ty * 8];
            *(float4*)&a[4] = *(const float4*)&As[kk][ty * 8 + 4];
            *(float4*)&b[0] = *(const float4*)&Bs[kk][tx * 8];
            *(float4*)&b[4] = *(const float4*)&Bs[kk][tx * 8 + 4];
            #pragma unroll
            for (int i = 0; i < 8; i++)
                #pragma unroll
                for (int j = 0; j < 8; j++)
                    acc[i][j] = fmaf(a[i], b[j], acc[i][j]);
        }
    }

    float* __restrict__ dst = (mat == 0) ? g_q : (mat == 1) ? g_k : g_v;

    #pragma unroll
    for (int i = 0; i < 8; i++) {
        const int row  = bm + ty * 8 + i;
        const int bidx = row >> 11;          // /S_
        const int s    = row & (S_ - 1);
        #pragma unroll
        for (int j = 0; j < 8; j++) {
            const int col = n0 + tx * 8 + j;     // 0..1023 within this matrix
            const int h   = col >> 6;
            const int d   = col & 63;
            float v = acc[i][j] + bvec[col];
            if (mat < 2 && d < ROT_) {
                // degenerate rotary: elementwise (cos -/+ sin)
                const float sn = sinu[(((bidx * 2 + 0) * S_ + s) << 5) + d];
                const float cs = sinu[(((bidx * 2 + 1) * S_ + s) << 5) + d];
                v *= (d & 1) ? (cs + sn) : (cs - sn);
            }
            if (mat == 0) v *= 0.125f;           // 1/sqrt(D)
            dst[(((size_t)bidx * H_ + h) * S_ + s) * D_ + d] = v;
        }
    }
}

// ---------------------------------------------------------------------------
// Kernel 2: flash attention per (b, h).  64 q-rows per block, 32-key chunks,
// online softmax.  256 threads: (ty,tx) = (tid/16, tid%16);
// S-tile: thread owns 4 rows x 2 key-cols; O-tile: 4 rows x 4 d-cols.
// P rows live entirely within one 16-lane subgroup -> __syncwarp suffices.
// ---------------------------------------------------------------------------
__global__ __launch_bounds__(256) void attn_kernel(const float* __restrict__ bias)
{
    const int bidx = blockIdx.z;
    const int h    = blockIdx.y;
    const int q0   = blockIdx.x * 64;
    const int tid  = threadIdx.x;
    const int tx   = tid & 15;
    const int ty   = tid >> 4;

    __shared__ float qs[64][68];    // [q-row][d], padded
    __shared__ float kst[64][36];   // transposed: [d][key]
    __shared__ float vs[32][68];    // [key][d]
    __shared__ float ps[64][36];    // [q-row][key]

    const float* __restrict__ qptr  = g_q + (((size_t)bidx * H_ + h) * S_ + q0) * D_;
    const float* __restrict__ kbase = g_k + (((size_t)bidx * H_ + h) * S_) * D_;
    const float* __restrict__ vbase = g_v + (((size_t)bidx * H_ + h) * S_) * D_;

    // load q tile (64x64)
    #pragma unroll
    for (int r = 0; r < 4; r++) {
        const int row = (tid >> 4) + r * 16;
        const int c4  = (tid & 15) * 4;
        *(float4*)&qs[row][c4] = *(const float4*)&qptr[(size_t)row * D_ + c4];
    }

    float m[4], l[4], acc[4][4];
    #pragma unroll
    for (int ii = 0; ii < 4; ii++) {
        m[ii] = -1e30f; l[ii] = 0.0f;
        #pragma unroll
        for (int jj = 0; jj < 4; jj++) acc[ii][jj] = 0.0f;
    }

    for (int kt = 0; kt < S_; kt += 32) {
        __syncthreads();   // qs ready (1st iter) / previous O-gemm done with vs,kst
        // load K (transposed into kst) and V
        #pragma unroll
        for (int r = 0; r < 2; r++) {
            const int i   = tid + r * 256;
            const int key = i >> 4;             // 0..31
            const int c4  = (i & 15) * 4;       // 0..60
            float4 kv = *(const float4*)&kbase[(size_t)(kt + key) * D_ + c4];
            kst[c4 + 0][key] = kv.x;
            kst[c4 + 1][key] = kv.y;
            kst[c4 + 2][key] = kv.z;
            kst[c4 + 3][key] = kv.w;
            *(float4*)&vs[key][c4] = *(const float4*)&vbase[(size_t)(kt + key) * D_ + c4];
        }
        __syncthreads();

        // S = q @ k^T  (64x32, K=64)
        float sc[4][2];
        #pragma unroll
        for (int ii = 0; ii < 4; ii++) { sc[ii][0] = 0.0f; sc[ii][1] = 0.0f; }

        #pragma unroll
        for (int d4 = 0; d4 < 16; d4++) {
            float qv[4][4];
            #pragma unroll
            for (int ii = 0; ii < 4; ii++)
                *(float4*)qv[ii] = *(const float4*)&qs[4 * ty + ii][d4 * 4];
            #pragma unroll
            for (int e = 0; e < 4; e++) {
                const float2 kv = *(const float2*)&kst[d4 * 4 + e][2 * tx];
                #pragma unroll
                for (int ii = 0; ii < 4; ii++) {
                    sc[ii][0] = fmaf(qv[ii][e], kv.x, sc[ii][0]);
                    sc[ii][1] = fmaf(qv[ii][e], kv.y, sc[ii][1]);
                }
            }
        }

        // add attention bias
        #pragma unroll
        for (int ii = 0; ii < 4; ii++) {
            const size_t boff = ((size_t)bidx * S_ + (q0 + 4 * ty + ii)) * S_ + kt + 2 * tx;
            sc[ii][0] += bias[boff + 0];
            sc[ii][1] += bias[boff + 1];
        }

        // online softmax update
        #pragma unroll
        for (int ii = 0; ii < 4; ii++) {
            float mx = fmaxf(sc[ii][0], sc[ii][1]);
            #pragma unroll
            for (int off = 8; off >= 1; off >>= 1)
                mx = fmaxf(mx, __shfl_xor_sync(0xffffffffu, mx, off, 16));
            const float mi   = fmaxf(m[ii], mx);
            const float corr = __expf(m[ii] - mi);
            const float p0   = __expf(sc[ii][0] - mi);
            const float p1   = __expf(sc[ii][1] - mi);
            float rs = p0 + p1;
            #pragma unroll
            for (int off = 8; off >= 1; off >>= 1)
                rs += __shfl_xor_sync(0xffffffffu, rs, off, 16);
            l[ii] = l[ii] * corr + rs;
            m[ii] = mi;
            #pragma unroll
            for (int jj = 0; jj < 4; jj++) acc[ii][jj] *= corr;
            ps[4 * ty + ii][2 * tx + 0] = p0;
            ps[4 * ty + ii][2 * tx + 1] = p1;
        }
        __syncwarp();   // P rows written & read by the same 16-lane group

        // O += P @ V  (64x64, K=32)
        #pragma unroll 8
        for (int j = 0; j < 32; j++) {
            const float4 vv = *(const float4*)&vs[j][tx * 4];
            #pragma unroll
            for (int ii = 0; ii < 4; ii++) {
                const float p = ps[4 * ty + ii][j];
                acc[ii][0] = fmaf(p, vv.x, acc[ii][0]);
                acc[ii][1] = fmaf(p, vv.y, acc[ii][1]);
                acc[ii][2] = fmaf(p, vv.z, acc[ii][2]);
                acc[ii][3] = fmaf(p, vv.w, acc[ii][3]);
            }
        }
    }

    // normalize + write [B,S,H*D]
    #pragma unroll
    for (int ii = 0; ii < 4; ii++) {
        const float inv = 1.0f / l[ii];
        float4 o;
        o.x = acc[ii][0] * inv;
        o.y = acc[ii][1] * inv;
        o.z = acc[ii][2] * inv;
        o.w = acc[ii][3] * inv;
        const int q = q0 + 4 * ty + ii;
        *(float4*)&g_attn[((size_t)(bidx * S_ + q)) * HID_ + h * D_ + tx * 4] = o;
    }
}

// ---------------------------------------------------------------------------
// Kernel 3: output projection.  out[4096 x 1024] = g_attn @ Wo.
// ---------------------------------------------------------------------------
__global__ __launch_bounds__(256) void proj_kernel(
    const float* __restrict__ Wo, float* __restrict__ out)
{
    const int bn = blockIdx.x * 128;
    const int bm = blockIdx.y * 128;

    __shared__ float As[16][132];
    __shared__ float Bs[16][128];

    const int tid  = threadIdx.x;
    const int tx   = tid & 15;
    const int ty   = tid >> 4;
    const int arow = tid >> 2;
    const int acol = (tid & 3) << 2;
    const int brow = tid >> 5;
    const int bcol = (tid & 31) << 2;

    float acc[8][8];
    #pragma unroll
    for (int i = 0; i < 8; i++)
        #pragma unroll
        for (int j = 0; j < 8; j++) acc[i][j] = 0.0f;

    for (int kt = 0; kt < HID_; kt += 16) {
        float4 a0 = *(const float4*)&g_attn[(size_t)(bm + arow)      * HID_ + kt + acol];
        float4 a1 = *(const float4*)&g_attn[(size_t)(bm + arow + 64) * HID_ + kt + acol];
        float4 w0 = *(const float4*)&Wo[(size_t)(kt + brow)     * HID_ + bn + bcol];
        float4 w1 = *(const float4*)&Wo[(size_t)(kt + brow + 8) * HID_ + bn + bcol];

        __syncthreads();
        As[acol + 0][arow]      = a0.x;
        As[acol + 1][arow]      = a0.y;
        As[acol + 2][arow]      = a0.z;
        As[acol + 3][arow]      = a0.w;
        As[acol + 0][arow + 64] = a1.x;
        As[acol + 1][arow + 64] = a1.y;
        As[acol + 2][arow + 64] = a1.z;
        As[acol + 3][arow + 64] = a1.w;
        *(float4*)&Bs[brow][bcol]     = w0;
        *(float4*)&Bs[brow + 8][bcol] = w1;
        __syncthreads();

        #pragma unroll
        for (int kk = 0; kk < 16; kk++) {
            float a[8], b[8];
            *(float4*)&a[0] = *(const float4*)&As[kk][ty * 8];
            *(float4*)&a[4] = *(const float4*)&As[kk][ty * 8 + 4];
            *(float4*)&b[0] = *(const float4*)&Bs[kk][tx * 8];
            *(float4*)&b[4] = *(const float4*)&Bs[kk][tx * 8 + 4];
            #pragma unroll
            for (int i = 0; i < 8; i++)
                #pragma unroll
                for (int j = 0; j < 8; j++)
                    acc[i][j] = fmaf(a[i], b[j], acc[i][j]);
        }
    }

    #pragma unroll
    for (int i = 0; i < 8; i++) {
        const int row = bm + ty * 8 + i;
        #pragma unroll
        for (int j = 0; j < 8; j++) {
            const int col = bn + tx * 8 + j;
            out[(size_t)row * HID_ + col] = acc[i][j];
        }
    }
}

// ---------------------------------------------------------------------------
extern "C" void kernel_launch(void* const* d_in, const int* in_sizes, int n_in,
                              void* d_out, int out_size)
{
    const float* x    = (const float*)d_in[0];
    const float* sinu = (const float*)d_in[1];
    const float* bias = (const float*)d_in[2];
    const float* Wq   = (const float*)d_in[3];
    const float* bq   = (const float*)d_in[4];
    const float* Wk   = (const float*)d_in[5];
    const float* bk   = (const float*)d_in[6];
    const float* Wv   = (const float*)d_in[7];
    const float* bv   = (const float*)d_in[8];
    const float* Wo   = (const float*)d_in[9];
    float* out = (float*)d_out;

    qkv_kernel<<<dim3(24, 32), 256>>>(x, sinu, Wq, bq, Wk, bk, Wv, bv);
    attn_kernel<<<dim3(S_ / 64, H_, B_), 256>>>(bias);
    proj_kernel<<<dim3(8, 32), 256>>>(Wo, out);
}

// round 3
// speedup vs baseline: 2.1525x; 2.1525x over previous
#include <cuda_runtime.h>
#include <cuda_bf16.h>

#define B_   2
#define S_   2048
#define H_   16
#define D_   64
#define HID_ 1024
#define ROT_ 32
#define BS_  (B_*S_)

// Scratch (allocation-free rule: __device__ globals)
__device__ float g_q[(size_t)B_*H_*S_*D_];
__device__ float g_k[(size_t)B_*H_*S_*D_];
__device__ float g_v[(size_t)B_*H_*S_*D_];
__device__ float g_attn[(size_t)BS_*HID_];

// ---------------------------------------------------------------------------
// bf16x3 helpers: x = hi + lo with both bf16; products use hi*hi+hi*lo+lo*hi.
// ---------------------------------------------------------------------------
__device__ __forceinline__ unsigned pack_bf(__nv_bfloat16 a, __nv_bfloat16 b) {
    __nv_bfloat162 p;
    p.x = a; p.y = b;
    return *(unsigned*)&p;
}

__device__ __forceinline__ void split2(float x, float y, unsigned& hi, unsigned& lo) {
    __nv_bfloat16 hx = __float2bfloat16(x);
    __nv_bfloat16 hy = __float2bfloat16(y);
    __nv_bfloat16 lx = __float2bfloat16(x - __bfloat162float(hx));
    __nv_bfloat16 ly = __float2bfloat16(y - __bfloat162float(hy));
    hi = pack_bf(hx, hy);
    lo = pack_bf(lx, ly);
}

// D(16x8,f32) += A(16x16,bf16,row) * B(16x8,bf16,col)
__device__ __forceinline__ void mma_bf16(float* d, const unsigned* a, const unsigned* b) {
    asm volatile(
        "mma.sync.aligned.m16n8k16.row.col.f32.bf16.bf16.f32 "
        "{%0,%1,%2,%3},{%4,%5,%6,%7},{%8,%9},{%0,%1,%2,%3};"
        : "+f"(d[0]), "+f"(d[1]), "+f"(d[2]), "+f"(d[3])
        : "r"(a[0]), "r"(a[1]), "r"(a[2]), "r"(a[3]), "r"(b[0]), "r"(b[1]));
}

// ---------------------------------------------------------------------------
// Kernel 1: fused QKV GEMM (bf16x3 mma).  C[4096 x 3072] = x @ [Wq|Wk|Wv]+b,
// rope-scale + 1/sqrt(D) fused in epilogue.  Writes [B,H,S,D].
// 256 thr = 8 warps (2x4); block tile 128x128, BK=32; warp tile 64x32.
// ---------------------------------------------------------------------------
__global__ __launch_bounds__(256) void qkv_kernel(
    const float* __restrict__ x, const float* __restrict__ sinu,
    const float* __restrict__ Wq, const float* __restrict__ bq,
    const float* __restrict__ Wk, const float* __restrict__ bk,
    const float* __restrict__ Wv, const float* __restrict__ bv)
{
    const int bn  = blockIdx.x * 128;
    const int bm  = blockIdx.y * 128;
    const int mat = bn >> 10;                   // 0=q,1=k,2=v
    const float* __restrict__ W    = (mat == 0) ? Wq : (mat == 1) ? Wk : Wv;
    const float* __restrict__ bvec = (mat == 0) ? bq : (mat == 1) ? bk : bv;
    const int n0 = bn & (HID_ - 1);

    __shared__ unsigned AsH[128][20], AsL[128][20];   // [m][kword], 16 + pad4
    __shared__ unsigned BsH[16][132], BsL[16][132];   // [kword][n]

    const int tid  = threadIdx.x;
    const int lane = tid & 31;
    const int g    = lane >> 2;
    const int t    = lane & 3;
    const int wm   = (tid >> 5) >> 2;   // 0..1
    const int wn   = (tid >> 5) & 3;    // 0..3

    float acc[4][4][4];
    #pragma unroll
    for (int i = 0; i < 4; i++)
        #pragma unroll
        for (int j = 0; j < 4; j++)
            #pragma unroll
            for (int e = 0; e < 4; e++) acc[i][j][e] = 0.0f;

    const int ar  = tid >> 3;           // A rows, 4 passes of 32
    const int acf = (tid & 7) * 4;      // A float col
    const int kwp = tid >> 5;           // B kword 0..7, 2 passes
    const int bn4 = (tid & 31) * 4;     // B n col

    for (int kt = 0; kt < HID_; kt += 32) {
        float4 av[4], w0[2], w1[2];
        #pragma unroll
        for (int p = 0; p < 4; p++)
            av[p] = *(const float4*)&x[(size_t)(bm + ar + p * 32) * HID_ + kt + acf];
        #pragma unroll
        for (int p = 0; p < 2; p++) {
            const int kw = kwp + p * 8;
            w0[p] = *(const float4*)&W[(size_t)(kt + kw * 2)     * HID_ + n0 + bn4];
            w1[p] = *(const float4*)&W[(size_t)(kt + kw * 2 + 1) * HID_ + n0 + bn4];
        }
        __syncthreads();
        #pragma unroll
        for (int p = 0; p < 4; p++) {
            uint2 hc, lc;
            split2(av[p].x, av[p].y, hc.x, lc.x);
            split2(av[p].z, av[p].w, hc.y, lc.y);
            *(uint2*)&AsH[ar + p * 32][acf >> 1] = hc;
            *(uint2*)&AsL[ar + p * 32][acf >> 1] = lc;
        }
        #pragma unroll
        for (int p = 0; p < 2; p++) {
            const int kw = kwp + p * 8;
            uint4 hc, lc;
            split2(w0[p].x, w1[p].x, hc.x, lc.x);
            split2(w0[p].y, w1[p].y, hc.y, lc.y);
            split2(w0[p].z, w1[p].z, hc.z, lc.z);
            split2(w0[p].w, w1[p].w, hc.w, lc.w);
            *(uint4*)&BsH[kw][bn4] = hc;
            *(uint4*)&BsL[kw][bn4] = lc;
        }
        __syncthreads();

        #pragma unroll
        for (int ks = 0; ks < 2; ks++) {
            unsigned aH[4][4], aL[4][4], bH[4][2], bL[4][2];
            const int kc = ks * 8 + t;
            #pragma unroll
            for (int mt = 0; mt < 4; mt++) {
                const int rb = wm * 64 + mt * 16;
                aH[mt][0] = AsH[rb + g][kc];         aL[mt][0] = AsL[rb + g][kc];
                aH[mt][1] = AsH[rb + 8 + g][kc];     aL[mt][1] = AsL[rb + 8 + g][kc];
                aH[mt][2] = AsH[rb + g][kc + 4];     aL[mt][2] = AsL[rb + g][kc + 4];
                aH[mt][3] = AsH[rb + 8 + g][kc + 4]; aL[mt][3] = AsL[rb + 8 + g][kc + 4];
            }
            #pragma unroll
            for (int nt = 0; nt < 4; nt++) {
                const int cb = wn * 32 + nt * 8 + g;
                bH[nt][0] = BsH[kc][cb];     bL[nt][0] = BsL[kc][cb];
                bH[nt][1] = BsH[kc + 4][cb]; bL[nt][1] = BsL[kc + 4][cb];
            }
            #pragma unroll
            for (int mt = 0; mt < 4; mt++)
                #pragma unroll
                for (int nt = 0; nt < 4; nt++) {
                    mma_bf16(acc[mt][nt], aH[mt], bH[nt]);
                    mma_bf16(acc[mt][nt], aH[mt], bL[nt]);
                    mma_bf16(acc[mt][nt], aL[mt], bH[nt]);
                }
        }
    }

    float* __restrict__ dst = (mat == 0) ? g_q : (mat == 1) ? g_k : g_v;

    #pragma unroll
    for (int mt = 0; mt < 4; mt++) {
        #pragma unroll
        for (int nt = 0; nt < 4; nt++) {
            const int colg = bn + wn * 32 + nt * 8 + t * 2;
            const int cm   = colg & (HID_ - 1);
            const int hh   = cm >> 6;
            const int d0   = cm & 63;
            #pragma unroll
            for (int half = 0; half < 2; half++) {
                const int row  = bm + wm * 64 + mt * 16 + g + half * 8;
                const int bidx = row >> 11;
                const int s    = row & (S_ - 1);
                float v0 = acc[mt][nt][half * 2 + 0] + bvec[cm];
                float v1 = acc[mt][nt][half * 2 + 1] + bvec[cm + 1];
                if (mat < 2 && d0 < ROT_) {
                    const float sn0 = sinu[(((bidx * 2 + 0) * S_ + s) << 5) + d0];
                    const float cs0 = sinu[(((bidx * 2 + 1) * S_ + s) << 5) + d0];
                    const float sn1 = sinu[(((bidx * 2 + 0) * S_ + s) << 5) + d0 + 1];
                    const float cs1 = sinu[(((bidx * 2 + 1) * S_ + s) << 5) + d0 + 1];
                    v0 *= (cs0 - sn0);
                    v1 *= (cs1 + sn1);
                }
                if (mat == 0) { v0 *= 0.125f; v1 *= 0.125f; }
                float2 o = make_float2(v0, v1);
                *(float2*)&dst[(((size_t)bidx * H_ + hh) * S_ + s) * D_ + d0] = o;
            }
        }
    }
}

// ---------------------------------------------------------------------------
// Kernel 2: flash attention, bf16x3 mma.  Block = (b,h,64 q-rows), 128 thr.
// ---------------------------------------------------------------------------
__global__ __launch_bounds__(128) void attn_kernel(const float* __restrict__ bias)
{
    const int bidx = blockIdx.z;
    const int h    = blockIdx.y;
    const int q0   = blockIdx.x * 64;
    const int tid  = threadIdx.x;
    const int lane = tid & 31;
    const int g    = lane >> 2;
    const int t    = lane & 3;
    const int wq   = tid >> 5;
    const int rb   = wq * 16;

    __shared__ unsigned KsH[32][36], KsL[32][36];   // [key][dword]
    __shared__ unsigned VsH[16][68], VsL[16][68];   // [keyword][d]
    __shared__ unsigned PsH[64][20], PsL[64][20];   // [q][keyword]

    const float* __restrict__ qptr  = g_q + (((size_t)bidx * H_ + h) * S_ + q0) * D_;
    const float* __restrict__ kbase = g_k + (((size_t)bidx * H_ + h) * S_) * D_;
    const float* __restrict__ vbase = g_v + (((size_t)bidx * H_ + h) * S_) * D_;

    // Q fragments direct from gmem, register-resident hi/lo (16 x 64)
    unsigned qaH[4][4], qaL[4][4];
    #pragma unroll
    for (int w = 0; w < 4; w++) {
        const int c = w * 16 + t * 2;
        float2 e0 = *(const float2*)&qptr[(size_t)(rb + g)     * D_ + c];
        float2 e1 = *(const float2*)&qptr[(size_t)(rb + 8 + g) * D_ + c];
        float2 e2 = *(const float2*)&qptr[(size_t)(rb + g)     * D_ + c + 8];
        float2 e3 = *(const float2*)&qptr[(size_t)(rb + 8 + g) * D_ + c + 8];
        split2(e0.x, e0.y, qaH[w][0], qaL[w][0]);
        split2(e1.x, e1.y, qaH[w][1], qaL[w][1]);
        split2(e2.x, e2.y, qaH[w][2], qaL[w][2]);
        split2(e3.x, e3.y, qaH[w][3], qaL[w][3]);
    }

    float oacc[8][4];
    #pragma unroll
    for (int i = 0; i < 8; i++)
        #pragma unroll
        for (int e = 0; e < 4; e++) oacc[i][e] = 0.0f;
    float m0 = -1e30f, m1 = -1e30f, l0 = 0.0f, l1 = 0.0f;

    for (int kt = 0; kt < S_; kt += 32) {
        __syncthreads();
        // K: [key][dword] pairs along d (natural layout)
        #pragma unroll
        for (int p = 0; p < 4; p++) {
            const int i   = tid + p * 128;
            const int key = i >> 4;
            const int c4  = (i & 15) * 4;
            float4 kv = *(const float4*)&kbase[(size_t)(kt + key) * D_ + c4];
            uint2 hc, lc;
            split2(kv.x, kv.y, hc.x, lc.x);
            split2(kv.z, kv.w, hc.y, lc.y);
            *(uint2*)&KsH[key][c4 >> 1] = hc;
            *(uint2*)&KsL[key][c4 >> 1] = lc;
        }
        // V: [keyword][d] pairs along key (pack from two adjacent key rows)
        #pragma unroll
        for (int p = 0; p < 2; p++) {
            const int kw = (tid >> 4) + p * 8;
            const int c4 = (tid & 15) * 4;
            float4 v0 = *(const float4*)&vbase[(size_t)(kt + kw * 2)     * D_ + c4];
            float4 v1 = *(const float4*)&vbase[(size_t)(kt + kw * 2 + 1) * D_ + c4];
            uint4 hc, lc;
            split2(v0.x, v1.x, hc.x, lc.x);
            split2(v0.y, v1.y, hc.y, lc.y);
            split2(v0.z, v1.z, hc.z, lc.z);
            split2(v0.w, v1.w, hc.w, lc.w);
            *(uint4*)&VsH[kw][c4] = hc;
            *(uint4*)&VsL[kw][c4] = lc;
        }
        __syncthreads();

        // S = Q K^T : 16x32, K=64 (4 windows of k16)
        float sacc[4][4];
        #pragma unroll
        for (int nt = 0; nt < 4; nt++)
            #pragma unroll
            for (int e = 0; e < 4; e++) sacc[nt][e] = 0.0f;

        #pragma unroll
        for (int w = 0; w < 4; w++) {
            const int kc = w * 8 + t;
            #pragma unroll
            for (int nt = 0; nt < 4; nt++) {
                unsigned bHf[2], bLf[2];
                bHf[0] = KsH[nt * 8 + g][kc];     bLf[0] = KsL[nt * 8 + g][kc];
                bHf[1] = KsH[nt * 8 + g][kc + 4]; bLf[1] = KsL[nt * 8 + g][kc + 4];
                mma_bf16(sacc[nt], qaH[w], bHf);
                mma_bf16(sacc[nt], qaH[w], bLf);
                mma_bf16(sacc[nt], qaL[w], bHf);
            }
        }

        // + attention bias
        #pragma unroll
        for (int nt = 0; nt < 4; nt++) {
            const size_t b0off = ((size_t)bidx * S_ + (q0 + rb + g)) * S_ + kt + nt * 8 + t * 2;
            const float2 bb0 = *(const float2*)&bias[b0off];
            const float2 bb1 = *(const float2*)&bias[b0off + (size_t)8 * S_];
            sacc[nt][0] += bb0.x; sacc[nt][1] += bb0.y;
            sacc[nt][2] += bb1.x; sacc[nt][3] += bb1.y;
        }

        // online softmax (rows g and g+8)
        float mx0 = -1e30f, mx1 = -1e30f;
        #pragma unroll
        for (int nt = 0; nt < 4; nt++) {
            mx0 = fmaxf(mx0, fmaxf(sacc[nt][0], sacc[nt][1]));
            mx1 = fmaxf(mx1, fmaxf(sacc[nt][2], sacc[nt][3]));
        }
        mx0 = fmaxf(mx0, __shfl_xor_sync(0xffffffffu, mx0, 1));
        mx0 = fmaxf(mx0, __shfl_xor_sync(0xffffffffu, mx0, 2));
        mx1 = fmaxf(mx1, __shfl_xor_sync(0xffffffffu, mx1, 1));
        mx1 = fmaxf(mx1, __shfl_xor_sync(0xffffffffu, mx1, 2));
        const float mi0 = fmaxf(m0, mx0), mi1 = fmaxf(m1, mx1);
        const float c0 = __expf(m0 - mi0), c1 = __expf(m1 - mi1);
        m0 = mi0; m1 = mi1;
        float rs0 = 0.0f, rs1 = 0.0f;
        #pragma unroll
        for (int nt = 0; nt < 4; nt++) {
            sacc[nt][0] = __expf(sacc[nt][0] - mi0);
            sacc[nt][1] = __expf(sacc[nt][1] - mi0);
            sacc[nt][2] = __expf(sacc[nt][2] - mi1);
            sacc[nt][3] = __expf(sacc[nt][3] - mi1);
            rs0 += sacc[nt][0] + sacc[nt][1];
            rs1 += sacc[nt][2] + sacc[nt][3];
        }
        rs0 += __shfl_xor_sync(0xffffffffu, rs0, 1);
        rs0 += __shfl_xor_sync(0xffffffffu, rs0, 2);
        rs1 += __shfl_xor_sync(0xffffffffu, rs1, 1);
        rs1 += __shfl_xor_sync(0xffffffffu, rs1, 2);
        l0 = l0 * c0 + rs0;
        l1 = l1 * c1 + rs1;
        #pragma unroll
        for (int nt = 0; nt < 8; nt++) {
            oacc[nt][0] *= c0; oacc[nt][1] *= c0;
            oacc[nt][2] *= c1; oacc[nt][3] *= c1;
        }

        // P -> smem hi/lo, packed pairs along key
        #pragma unroll
        for (int nt = 0; nt < 4; nt++) {
            unsigned hp, lp;
            split2(sacc[nt][0], sacc[nt][1], hp, lp);
            PsH[rb + g][nt * 4 + t] = hp;
            PsL[rb + g][nt * 4 + t] = lp;
            split2(sacc[nt][2], sacc[nt][3], hp, lp);
            PsH[rb + 8 + g][nt * 4 + t] = hp;
            PsL[rb + 8 + g][nt * 4 + t] = lp;
        }
        __syncwarp();

        // O += P V : 16x64, K=32 (2 windows of k16)
        #pragma unroll
        for (int w = 0; w < 2; w++) {
            unsigned paH[4], paL[4];
            const int kc = w * 8 + t;
            paH[0] = PsH[rb + g][kc];         paL[0] = PsL[rb + g][kc];
            paH[1] = PsH[rb + 8 + g][kc];     paL[1] = PsL[rb + 8 + g][kc];
            paH[2] = PsH[rb + g][kc + 4];     paL[2] = PsL[rb + g][kc + 4];
            paH[3] = PsH[rb + 8 + g][kc + 4]; paL[3] = PsL[rb + 8 + g][kc + 4];
            #pragma unroll
            for (int nt = 0; nt < 8; nt++) {
                unsigned bHf[2], bLf[2];
                bHf[0] = VsH[kc][nt * 8 + g];     bLf[0] = VsL[kc][nt * 8 + g];
                bHf[1] = VsH[kc + 4][nt * 8 + g]; bLf[1] = VsL[kc + 4][nt * 8 + g];
                mma_bf16(oacc[nt], paH, bHf);
                mma_bf16(oacc[nt], paH, bLf);
                mma_bf16(oacc[nt], paL, bHf);
            }
        }
    }

    // normalize + write [B,S,HID]
    const float inv0 = 1.0f / l0, inv1 = 1.0f / l1;
    #pragma unroll
    for (int nt = 0; nt < 8; nt++) {
        const int col = h * D_ + nt * 8 + t * 2;
        const int r0  = q0 + rb + g;
        float2 o0 = make_float2(oacc[nt][0] * inv0, oacc[nt][1] * inv0);
        float2 o1 = make_float2(oacc[nt][2] * inv1, oacc[nt][3] * inv1);
        *(float2*)&g_attn[((size_t)(bidx * S_ + r0)) * HID_ + col]     = o0;
        *(float2*)&g_attn[((size_t)(bidx * S_ + r0 + 8)) * HID_ + col] = o1;
    }
}

// ---------------------------------------------------------------------------
// Kernel 3: output projection (bf16x3 mma).  out[4096 x 1024] = g_attn @ Wo.
// ---------------------------------------------------------------------------
__global__ __launch_bounds__(256) void proj_kernel(
    const float* __restrict__ Wo, float* __restrict__ out)
{
    const int bn = blockIdx.x * 128;
    const int bm = blockIdx.y * 128;

    __shared__ unsigned AsH[128][20], AsL[128][20];
    __shared__ unsigned BsH[16][132], BsL[16][132];

    const int tid  = threadIdx.x;
    const int lane = tid & 31;
    const int g    = lane >> 2;
    const int t    = lane & 3;
    const int wm   = (tid >> 5) >> 2;
    const int wn   = (tid >> 5) & 3;

    float acc[4][4][4];
    #pragma unroll
    for (int i = 0; i < 4; i++)
        #pragma unroll
        for (int j = 0; j < 4; j++)
            #pragma unroll
            for (int e = 0; e < 4; e++) acc[i][j][e] = 0.0f;

    const int ar  = tid >> 3;
    const int acf = (tid & 7) * 4;
    const int kwp = tid >> 5;
    const int bn4 = (tid & 31) * 4;

    for (int kt = 0; kt < HID_; kt += 32) {
        float4 av[4], w0[2], w1[2];
        #pragma unroll
        for (int p = 0; p < 4; p++)
            av[p] = *(const float4*)&g_attn[(size_t)(bm + ar + p * 32) * HID_ + kt + acf];
        #pragma unroll
        for (int p = 0; p < 2; p++) {
            const int kw = kwp + p * 8;
            w0[p] = *(const float4*)&Wo[(size_t)(kt + kw * 2)     * HID_ + bn + bn4];
            w1[p] = *(const float4*)&Wo[(size_t)(kt + kw * 2 + 1) * HID_ + bn + bn4];
        }
        __syncthreads();
        #pragma unroll
        for (int p = 0; p < 4; p++) {
            uint2 hc, lc;
            split2(av[p].x, av[p].y, hc.x, lc.x);
            split2(av[p].z, av[p].w, hc.y, lc.y);
            *(uint2*)&AsH[ar + p * 32][acf >> 1] = hc;
            *(uint2*)&AsL[ar + p * 32][acf >> 1] = lc;
        }
        #pragma unroll
        for (int p = 0; p < 2; p++) {
            const int kw = kwp + p * 8;
            uint4 hc, lc;
            split2(w0[p].x, w1[p].x, hc.x, lc.x);
            split2(w0[p].y, w1[p].y, hc.y, lc.y);
            split2(w0[p].z, w1[p].z, hc.z, lc.z);
            split2(w0[p].w, w1[p].w, hc.w, lc.w);
            *(uint4*)&BsH[kw][bn4] = hc;
            *(uint4*)&BsL[kw][bn4] = lc;
        }
        __syncthreads();

        #pragma unroll
        for (int ks = 0; ks < 2; ks++) {
            unsigned aH[4][4], aL[4][4], bH[4][2], bL[4][2];
            const int kc = ks * 8 + t;
            #pragma unroll
            for (int mt = 0; mt < 4; mt++) {
                const int rbm = wm * 64 + mt * 16;
                aH[mt][0] = AsH[rbm + g][kc];         aL[mt][0] = AsL[rbm + g][kc];
                aH[mt][1] = AsH[rbm + 8 + g][kc];     aL[mt][1] = AsL[rbm + 8 + g][kc];
                aH[mt][2] = AsH[rbm + g][kc + 4];     aL[mt][2] = AsL[rbm + g][kc + 4];
                aH[mt][3] = AsH[rbm + 8 + g][kc + 4]; aL[mt][3] = AsL[rbm + 8 + g][kc + 4];
            }
            #pragma unroll
            for (int nt = 0; nt < 4; nt++) {
                const int cb = wn * 32 + nt * 8 + g;
                bH[nt][0] = BsH[kc][cb];     bL[nt][0] = BsL[kc][cb];
                bH[nt][1] = BsH[kc + 4][cb]; bL[nt][1] = BsL[kc + 4][cb];
            }
            #pragma unroll
            for (int mt = 0; mt < 4; mt++)
                #pragma unroll
                for (int nt = 0; nt < 4; nt++) {
                    mma_bf16(acc[mt][nt], aH[mt], bH[nt]);
                    mma_bf16(acc[mt][nt], aH[mt], bL[nt]);
                    mma_bf16(acc[mt][nt], aL[mt], bH[nt]);
                }
        }
    }

    #pragma unroll
    for (int mt = 0; mt < 4; mt++) {
        #pragma unroll
        for (int nt = 0; nt < 4; nt++) {
            const int col = bn + wn * 32 + nt * 8 + t * 2;
            #pragma unroll
            for (int half = 0; half < 2; half++) {
                const int row = bm + wm * 64 + mt * 16 + g + half * 8;
                float2 o = make_float2(acc[mt][nt][half * 2], acc[mt][nt][half * 2 + 1]);
                *(float2*)&out[(size_t)row * HID_ + col] = o;
            }
        }
    }
}

// ---------------------------------------------------------------------------
extern "C" void kernel_launch(void* const* d_in, const int* in_sizes, int n_in,
                              void* d_out, int out_size)
{
    const float* x    = (const float*)d_in[0];
    const float* sinu = (const float*)d_in[1];
    const float* bias = (const float*)d_in[2];
    const float* Wq   = (const float*)d_in[3];
    const float* bq   = (const float*)d_in[4];
    const float* Wk   = (const float*)d_in[5];
    const float* bk   = (const float*)d_in[6];
    const float* Wv   = (const float*)d_in[7];
    const float* bv   = (const float*)d_in[8];
    const float* Wo   = (const float*)d_in[9];
    float* out = (float*)d_out;

    qkv_kernel<<<dim3(24, 32), 256>>>(x, sinu, Wq, bq, Wk, bk, Wv, bv);
    attn_kernel<<<dim3(S_ / 64, H_, B_), 128>>>(bias);
    proj_kernel<<<dim3(8, 32), 256>>>(Wo, out);
}

// round 4
// speedup vs baseline: 2.2672x; 1.0533x over previous
#include <cuda_runtime.h>
#include <cuda_bf16.h>

#define B_   2
#define S_   2048
#define H_   16
#define D_   64
#define HID_ 1024
#define ROT_ 32
#define BS_  (B_*S_)

// ---------------------------------------------------------------------------
// Device-global scratch (allocation-free rule)
// ---------------------------------------------------------------------------
__device__ unsigned g_xH[(size_t)BS_*HID_/2], g_xL[(size_t)BS_*HID_/2];
__device__ unsigned g_WqH[HID_*HID_/2], g_WqL[HID_*HID_/2];
__device__ unsigned g_WkH[HID_*HID_/2], g_WkL[HID_*HID_/2];
__device__ unsigned g_WvH[HID_*HID_/2], g_WvL[HID_*HID_/2];
__device__ unsigned g_WoH[HID_*HID_/2], g_WoL[HID_*HID_/2];
__device__ unsigned g_qH[(size_t)B_*H_*S_*D_/2], g_qL[(size_t)B_*H_*S_*D_/2];
__device__ unsigned g_kH[(size_t)B_*H_*S_*D_/2], g_kL[(size_t)B_*H_*S_*D_/2];
__device__ float    g_v[(size_t)B_*H_*S_*D_];
__device__ unsigned g_attnH[(size_t)BS_*HID_/2], g_attnL[(size_t)BS_*HID_/2];

// ---------------------------------------------------------------------------
// bf16x3 helpers
// ---------------------------------------------------------------------------
__device__ __forceinline__ unsigned pack_bf(__nv_bfloat16 a, __nv_bfloat16 b) {
    __nv_bfloat162 p; p.x = a; p.y = b;
    return *(unsigned*)&p;
}
__device__ __forceinline__ void split2(float x, float y, unsigned& hi, unsigned& lo) {
    __nv_bfloat16 hx = __float2bfloat16(x);
    __nv_bfloat16 hy = __float2bfloat16(y);
    __nv_bfloat16 lx = __float2bfloat16(x - __bfloat162float(hx));
    __nv_bfloat16 ly = __float2bfloat16(y - __bfloat162float(hy));
    hi = pack_bf(hx, hy);
    lo = pack_bf(lx, ly);
}
__device__ __forceinline__ void mma_bf16(float* d, const unsigned* a, const unsigned* b) {
    asm volatile(
        "mma.sync.aligned.m16n8k16.row.col.f32.bf16.bf16.f32 "
        "{%0,%1,%2,%3},{%4,%5,%6,%7},{%8,%9},{%0,%1,%2,%3};"
        : "+f"(d[0]), "+f"(d[1]), "+f"(d[2]), "+f"(d[3])
        : "r"(a[0]), "r"(a[1]), "r"(a[2]), "r"(a[3]), "r"(b[0]), "r"(b[1]));
}
__device__ __forceinline__ void cp16(unsigned saddr, const void* gptr) {
    asm volatile("cp.async.ca.shared.global [%0], [%1], 16;" :: "r"(saddr), "l"(gptr));
}
#define CP_COMMIT() asm volatile("cp.async.commit_group;")

// ---------------------------------------------------------------------------
// Prep: convert x (pairs contiguous along k) and W (pairs along rows=k).
// ---------------------------------------------------------------------------
__global__ void prep_x(const float* __restrict__ x) {
    const int i = blockIdx.x * 256 + threadIdx.x;        // float4 index
    float4 v = ((const float4*)x)[i];
    uint2 h, l;
    split2(v.x, v.y, h.x, l.x);
    split2(v.z, v.w, h.y, l.y);
    ((uint2*)g_xH)[i] = h;
    ((uint2*)g_xL)[i] = l;
}

__global__ void prep_w(const float* __restrict__ W, int which) {
    unsigned* Hd = which == 0 ? g_WqH : which == 1 ? g_WkH : which == 2 ? g_WvH : g_WoH;
    unsigned* Ld = which == 0 ? g_WqL : which == 1 ? g_WkL : which == 2 ? g_WvL : g_WoL;
    const int j  = blockIdx.x * 256 + threadIdx.x;       // 0..131071
    const int kw = j >> 8;                               // 0..511
    const int n4 = (j & 255) * 4;
    float4 a = *(const float4*)&W[(size_t)(2 * kw)     * HID_ + n4];
    float4 b = *(const float4*)&W[(size_t)(2 * kw + 1) * HID_ + n4];
    uint4 h, l;
    split2(a.x, b.x, h.x, l.x);
    split2(a.y, b.y, h.y, l.y);
    split2(a.z, b.z, h.z, l.z);
    split2(a.w, b.w, h.w, l.w);
    *(uint4*)&Hd[(size_t)kw * HID_ + n4] = h;
    *(uint4*)&Ld[(size_t)kw * HID_ + n4] = l;
}

// ---------------------------------------------------------------------------
// GEMM smem layout (dynamic): AsH[2][128][20], AsL, BsH[2][16][132], BsL.
// Word offsets:
#define ASH_OFF 0
#define ASL_OFF 5120
#define BSH_OFF 10240
#define BSL_OFF 14464
#define GEMM_SMEM_BYTES ((14464 + 2*16*132) * 4)   // 74752

__device__ __forceinline__ void gemm_ld_stage(
    unsigned smemBase, int s, int tid, int bm, int n0, int ktw,
    const unsigned* __restrict__ AH, const unsigned* __restrict__ AL,
    const unsigned* __restrict__ WH, const unsigned* __restrict__ WL)
{
    #pragma unroll
    for (int p = 0; p < 2; p++) {
        const int c    = tid + p * 256;
        const int row  = c >> 2;
        const int w4   = (c & 3) * 4;
        const size_t ga = (size_t)(bm + row) * 512 + ktw + w4;
        cp16(smemBase + (ASH_OFF + s * 2560 + row * 20 + w4) * 4, &AH[ga]);
        cp16(smemBase + (ASL_OFF + s * 2560 + row * 20 + w4) * 4, &AL[ga]);
        const int rowb = c >> 5;
        const int w4b  = (c & 31) * 4;
        const size_t gb = (size_t)(ktw + rowb) * HID_ + n0 + w4b;
        cp16(smemBase + (BSH_OFF + s * 2112 + rowb * 132 + w4b) * 4, &WH[gb]);
        cp16(smemBase + (BSL_OFF + s * 2112 + rowb * 132 + w4b) * 4, &WL[gb]);
    }
}

// ---------------------------------------------------------------------------
// Kernel 1: fused QKV GEMM, cp.async double-buffered, pre-packed operands.
// ---------------------------------------------------------------------------
__global__ __launch_bounds__(256) void qkv_kernel(
    const float* __restrict__ sinu,
    const float* __restrict__ bq, const float* __restrict__ bk,
    const float* __restrict__ bv)
{
    extern __shared__ unsigned sm[];
    const unsigned smemBase = (unsigned)__cvta_generic_to_shared(sm);

    const int bn  = blockIdx.x * 128;
    const int bm  = blockIdx.y * 128;
    const int mat = bn >> 10;
    const unsigned* __restrict__ WH = mat == 0 ? g_WqH : mat == 1 ? g_WkH : g_WvH;
    const unsigned* __restrict__ WL = mat == 0 ? g_WqL : mat == 1 ? g_WkL : g_WvL;
    const float*    __restrict__ bvec = mat == 0 ? bq : mat == 1 ? bk : bv;
    const int n0 = bn & (HID_ - 1);

    const int tid  = threadIdx.x;
    const int lane = tid & 31;
    const int g    = lane >> 2;
    const int t    = lane & 3;
    const int wm   = (tid >> 5) >> 2;
    const int wn   = (tid >> 5) & 3;

    float acc[4][4][4];
    #pragma unroll
    for (int i = 0; i < 4; i++)
        #pragma unroll
        for (int j = 0; j < 4; j++)
            #pragma unroll
            for (int e = 0; e < 4; e++) acc[i][j][e] = 0.0f;

    gemm_ld_stage(smemBase, 0, tid, bm, n0, 0, g_xH, g_xL, WH, WL);
    CP_COMMIT();

    for (int it = 0; it < 32; it++) {
        const int buf = it & 1;
        if (it + 1 < 32) {
            gemm_ld_stage(smemBase, buf ^ 1, tid, bm, n0, (it + 1) * 16, g_xH, g_xL, WH, WL);
            CP_COMMIT();
            asm volatile("cp.async.wait_group 1;");
        } else {
            asm volatile("cp.async.wait_group 0;");
        }
        __syncthreads();

        #pragma unroll
        for (int ks = 0; ks < 2; ks++) {
            const int kc = ks * 8 + t;
            unsigned aH[4][4], aL[4][4], bH[4][2], bL[4][2];
            #pragma unroll
            for (int mt = 0; mt < 4; mt++) {
                const int rb = wm * 64 + mt * 16;
                aH[mt][0] = sm[ASH_OFF + buf*2560 + (rb + g)     * 20 + kc];
                aH[mt][1] = sm[ASH_OFF + buf*2560 + (rb + 8 + g) * 20 + kc];
                aH[mt][2] = sm[ASH_OFF + buf*2560 + (rb + g)     * 20 + kc + 4];
                aH[mt][3] = sm[ASH_OFF + buf*2560 + (rb + 8 + g) * 20 + kc + 4];
                aL[mt][0] = sm[ASL_OFF + buf*2560 + (rb + g)     * 20 + kc];
                aL[mt][1] = sm[ASL_OFF + buf*2560 + (rb + 8 + g) * 20 + kc];
                aL[mt][2] = sm[ASL_OFF + buf*2560 + (rb + g)     * 20 + kc + 4];
                aL[mt][3] = sm[ASL_OFF + buf*2560 + (rb + 8 + g) * 20 + kc + 4];
            }
            #pragma unroll
            for (int nt = 0; nt < 4; nt++) {
                const int cb = wn * 32 + nt * 8 + g;
                bH[nt][0] = sm[BSH_OFF + buf*2112 + kc       * 132 + cb];
                bH[nt][1] = sm[BSH_OFF + buf*2112 + (kc + 4) * 132 + cb];
                bL[nt][0] = sm[BSL_OFF + buf*2112 + kc       * 132 + cb];
                bL[nt][1] = sm[BSL_OFF + buf*2112 + (kc + 4) * 132 + cb];
            }
            #pragma unroll
            for (int mt = 0; mt < 4; mt++)
                #pragma unroll
                for (int nt = 0; nt < 4; nt++) {
                    mma_bf16(acc[mt][nt], aH[mt], bH[nt]);
                    mma_bf16(acc[mt][nt], aH[mt], bL[nt]);
                    mma_bf16(acc[mt][nt], aL[mt], bH[nt]);
                }
        }
        __syncthreads();
    }

    // epilogue: bias + rope + scale; pack q,k; f32 v.
    #pragma unroll
    for (int mt = 0; mt < 4; mt++) {
        #pragma unroll
        for (int nt = 0; nt < 4; nt++) {
            const int colg = bn + wn * 32 + nt * 8 + t * 2;
            const int cm   = colg & (HID_ - 1);
            const int hh   = cm >> 6;
            const int d0   = cm & 63;
            #pragma unroll
            for (int half = 0; half < 2; half++) {
                const int row  = bm + wm * 64 + mt * 16 + g + half * 8;
                const int bidx = row >> 11;
                const int s    = row & (S_ - 1);
                float v0 = acc[mt][nt][half * 2 + 0] + bvec[cm];
                float v1 = acc[mt][nt][half * 2 + 1] + bvec[cm + 1];
                if (mat < 2 && d0 < ROT_) {
                    const float sn0 = sinu[(((bidx * 2 + 0) * S_ + s) << 5) + d0];
                    const float cs0 = sinu[(((bidx * 2 + 1) * S_ + s) << 5) + d0];
                    const float sn1 = sinu[(((bidx * 2 + 0) * S_ + s) << 5) + d0 + 1];
                    const float cs1 = sinu[(((bidx * 2 + 1) * S_ + s) << 5) + d0 + 1];
                    v0 *= (cs0 - sn0);
                    v1 *= (cs1 + sn1);
                }
                const size_t base = ((size_t)bidx * H_ + hh) * S_ + s;
                if (mat == 2) {
                    *(float2*)&g_v[base * D_ + d0] = make_float2(v0, v1);
                } else {
                    if (mat == 0) { v0 *= 0.125f; v1 *= 0.125f; }
                    unsigned hw, lw;
                    split2(v0, v1, hw, lw);
                    if (mat == 0) {
                        g_qH[base * 32 + (d0 >> 1)] = hw;
                        g_qL[base * 32 + (d0 >> 1)] = lw;
                    } else {
                        g_kH[base * 32 + (d0 >> 1)] = hw;
                        g_kL[base * 32 + (d0 >> 1)] = lw;
                    }
                }
            }
        }
    }
}

// ---------------------------------------------------------------------------
// Kernel 2: flash attention.  256 thr, 128 q-rows/block, 32-key chunks.
// K double-buffered via cp.async (pre-packed); V register-pipelined.
// ---------------------------------------------------------------------------
__global__ __launch_bounds__(256) void attn_kernel(const float* __restrict__ bias)
{
    const int bidx = blockIdx.z;
    const int h    = blockIdx.y;
    const int q0   = blockIdx.x * 128;
    const int tid  = threadIdx.x;
    const int lane = tid & 31;
    const int g    = lane >> 2;
    const int t    = lane & 3;
    const int rb   = (tid >> 5) * 16;

    __shared__ unsigned KsH[2][32][36], KsL[2][32][36];
    __shared__ unsigned VsH[16][68],    VsL[16][68];
    __shared__ unsigned PsH[128][20],   PsL[128][20];

    const size_t bh = (size_t)bidx * H_ + h;
    const unsigned* __restrict__ qHp = g_qH + (bh * S_ + q0) * 32;
    const unsigned* __restrict__ qLp = g_qL + (bh * S_ + q0) * 32;
    const unsigned* __restrict__ kHp = g_kH + bh * S_ * 32;
    const unsigned* __restrict__ kLp = g_kL + bh * S_ * 32;
    const float*    __restrict__ vbase = g_v + bh * S_ * D_;

    // Q fragments straight from packed gmem
    unsigned qaH[4][4], qaL[4][4];
    #pragma unroll
    for (int w = 0; w < 4; w++) {
        qaH[w][0] = qHp[(rb + g)     * 32 + w * 8 + t];
        qaH[w][1] = qHp[(rb + 8 + g) * 32 + w * 8 + t];
        qaH[w][2] = qHp[(rb + g)     * 32 + w * 8 + t + 4];
        qaH[w][3] = qHp[(rb + 8 + g) * 32 + w * 8 + t + 4];
        qaL[w][0] = qLp[(rb + g)     * 32 + w * 8 + t];
        qaL[w][1] = qLp[(rb + 8 + g) * 32 + w * 8 + t];
        qaL[w][2] = qLp[(rb + g)     * 32 + w * 8 + t + 4];
        qaL[w][3] = qLp[(rb + 8 + g) * 32 + w * 8 + t + 4];
    }

    float oacc[8][4];
    #pragma unroll
    for (int i = 0; i < 8; i++)
        #pragma unroll
        for (int e = 0; e < 4; e++) oacc[i][e] = 0.0f;
    float m0 = -1e30f, m1 = -1e30f, l0 = 0.0f, l1 = 0.0f;

    // loader indices
    const int krow = tid >> 3, kw4 = (tid & 7) * 4;   // K cp.async
    const int vkw  = tid >> 4, vc4 = (tid & 15) * 4;  // V regs / store

    // preload chunk 0: K via cp.async, V into regs, bias into regs
    cp16((unsigned)__cvta_generic_to_shared(&KsH[0][krow][kw4]), &kHp[(size_t)krow * 32 + kw4]);
    cp16((unsigned)__cvta_generic_to_shared(&KsL[0][krow][kw4]), &kLp[(size_t)krow * 32 + kw4]);
    CP_COMMIT();
    float4 vr0 = *(const float4*)&vbase[(size_t)(2 * vkw)     * D_ + vc4];
    float4 vr1 = *(const float4*)&vbase[(size_t)(2 * vkw + 1) * D_ + vc4];
    float2 bb0[4], bb1[4];
    {
        const size_t brow0 = ((size_t)bidx * S_ + (q0 + rb + g)) * S_;
        #pragma unroll
        for (int nt = 0; nt < 4; nt++) {
            bb0[nt] = *(const float2*)&bias[brow0 + nt * 8 + t * 2];
            bb1[nt] = *(const float2*)&bias[brow0 + (size_t)8 * S_ + nt * 8 + t * 2];
        }
    }

    for (int c = 0; c < 64; c++) {
        const int buf = c & 1;
        asm volatile("cp.async.wait_group 0;");
        __syncthreads();                       // K[c] landed; all warps done prev iter

        // store V chunk c from regs (split-pack along key)
        {
            uint4 hc, lc;
            split2(vr0.x, vr1.x, hc.x, lc.x);
            split2(vr0.y, vr1.y, hc.y, lc.y);
            split2(vr0.z, vr1.z, hc.z, lc.z);
            split2(vr0.w, vr1.w, hc.w, lc.w);
            *(uint4*)&VsH[vkw][vc4] = hc;
            *(uint4*)&VsL[vkw][vc4] = lc;
        }
        // issue next chunk
        if (c + 1 < 64) {
            const int kt2 = (c + 1) * 32;
            cp16((unsigned)__cvta_generic_to_shared(&KsH[buf ^ 1][krow][kw4]),
                 &kHp[(size_t)(kt2 + krow) * 32 + kw4]);
            cp16((unsigned)__cvta_generic_to_shared(&KsL[buf ^ 1][krow][kw4]),
                 &kLp[(size_t)(kt2 + krow) * 32 + kw4]);
            CP_COMMIT();
            vr0 = *(const float4*)&vbase[(size_t)(kt2 + 2 * vkw)     * D_ + vc4];
            vr1 = *(const float4*)&vbase[(size_t)(kt2 + 2 * vkw + 1) * D_ + vc4];
        }
        __syncthreads();                       // Vs visible

        // S = Q K^T : 16x32, K=64
        float sacc[4][4];
        #pragma unroll
        for (int nt = 0; nt < 4; nt++)
            #pragma unroll
            for (int e = 0; e < 4; e++) sacc[nt][e] = 0.0f;
        #pragma unroll
        for (int w = 0; w < 4; w++) {
            const int kc = w * 8 + t;
            #pragma unroll
            for (int nt = 0; nt < 4; nt++) {
                unsigned bHf[2], bLf[2];
                bHf[0] = KsH[buf][nt * 8 + g][kc];
                bHf[1] = KsH[buf][nt * 8 + g][kc + 4];
                bLf[0] = KsL[buf][nt * 8 + g][kc];
                bLf[1] = KsL[buf][nt * 8 + g][kc + 4];
                mma_bf16(sacc[nt], qaH[w], bHf);
                mma_bf16(sacc[nt], qaH[w], bLf);
                mma_bf16(sacc[nt], qaL[w], bHf);
            }
        }

        // + bias (prefetched)
        #pragma unroll
        for (int nt = 0; nt < 4; nt++) {
            sacc[nt][0] += bb0[nt].x; sacc[nt][1] += bb0[nt].y;
            sacc[nt][2] += bb1[nt].x; sacc[nt][3] += bb1[nt].y;
        }

        // online softmax
        float mx0 = -1e30f, mx1 = -1e30f;
        #pragma unroll
        for (int nt = 0; nt < 4; nt++) {
            mx0 = fmaxf(mx0, fmaxf(sacc[nt][0], sacc[nt][1]));
            mx1 = fmaxf(mx1, fmaxf(sacc[nt][2], sacc[nt][3]));
        }
        mx0 = fmaxf(mx0, __shfl_xor_sync(0xffffffffu, mx0, 1));
        mx0 = fmaxf(mx0, __shfl_xor_sync(0xffffffffu, mx0, 2));
        mx1 = fmaxf(mx1, __shfl_xor_sync(0xffffffffu, mx1, 1));
        mx1 = fmaxf(mx1, __shfl_xor_sync(0xffffffffu, mx1, 2));
        const float mi0 = fmaxf(m0, mx0), mi1 = fmaxf(m1, mx1);
        const float c0 = __expf(m0 - mi0), c1 = __expf(m1 - mi1);
        m0 = mi0; m1 = mi1;
        float rs0 = 0.0f, rs1 = 0.0f;
        #pragma unroll
        for (int nt = 0; nt < 4; nt++) {
            sacc[nt][0] = __expf(sacc[nt][0] - mi0);
            sacc[nt][1] = __expf(sacc[nt][1] - mi0);
            sacc[nt][2] = __expf(sacc[nt][2] - mi1);
            sacc[nt][3] = __expf(sacc[nt][3] - mi1);
            rs0 += sacc[nt][0] + sacc[nt][1];
            rs1 += sacc[nt][2] + sacc[nt][3];
        }
        rs0 += __shfl_xor_sync(0xffffffffu, rs0, 1);
        rs0 += __shfl_xor_sync(0xffffffffu, rs0, 2);
        rs1 += __shfl_xor_sync(0xffffffffu, rs1, 1);
        rs1 += __shfl_xor_sync(0xffffffffu, rs1, 2);
        l0 = l0 * c0 + rs0;
        l1 = l1 * c1 + rs1;
        #pragma unroll
        for (int nt = 0; nt < 8; nt++) {
            oacc[nt][0] *= c0; oacc[nt][1] *= c0;
            oacc[nt][2] *= c1; oacc[nt][3] *= c1;
        }

        // P -> smem (hi/lo, pairs along key)
        #pragma unroll
        for (int nt = 0; nt < 4; nt++) {
            unsigned hp, lp;
            split2(sacc[nt][0], sacc[nt][1], hp, lp);
            PsH[rb + g][nt * 4 + t] = hp;
            PsL[rb + g][nt * 4 + t] = lp;
            split2(sacc[nt][2], sacc[nt][3], hp, lp);
            PsH[rb + 8 + g][nt * 4 + t] = hp;
            PsL[rb + 8 + g][nt * 4 + t] = lp;
        }
        __syncwarp();

        // O += P V : 16x64, K=32
        #pragma unroll
        for (int w = 0; w < 2; w++) {
            const int kc = w * 8 + t;
            unsigned paH[4], paL[4];
            paH[0] = PsH[rb + g][kc];         paL[0] = PsL[rb + g][kc];
            paH[1] = PsH[rb + 8 + g][kc];     paL[1] = PsL[rb + 8 + g][kc];
            paH[2] = PsH[rb + g][kc + 4];     paL[2] = PsL[rb + g][kc + 4];
            paH[3] = PsH[rb + 8 + g][kc + 4]; paL[3] = PsL[rb + 8 + g][kc + 4];
            #pragma unroll
            for (int nt = 0; nt < 8; nt++) {
                unsigned bHf[2], bLf[2];
                bHf[0] = VsH[kc][nt * 8 + g];     bLf[0] = VsL[kc][nt * 8 + g];
                bHf[1] = VsH[kc + 4][nt * 8 + g]; bLf[1] = VsL[kc + 4][nt * 8 + g];
                mma_bf16(oacc[nt], paH, bHf);
                mma_bf16(oacc[nt], paH, bLf);
                mma_bf16(oacc[nt], paL, bHf);
            }
        }

        // prefetch bias for next chunk (latency hidden by next iter's barriers)
        if (c + 1 < 64) {
            const size_t brow0 = ((size_t)bidx * S_ + (q0 + rb + g)) * S_ + (c + 1) * 32;
            #pragma unroll
            for (int nt = 0; nt < 4; nt++) {
                bb0[nt] = *(const float2*)&bias[brow0 + nt * 8 + t * 2];
                bb1[nt] = *(const float2*)&bias[brow0 + (size_t)8 * S_ + nt * 8 + t * 2];
            }
        }
    }

    // normalize + write packed [B,S,HID] for proj
    const float inv0 = 1.0f / l0, inv1 = 1.0f / l1;
    #pragma unroll
    for (int nt = 0; nt < 8; nt++) {
        const int col = h * D_ + nt * 8 + t * 2;
        const int r0  = q0 + rb + g;
        unsigned hw, lw;
        split2(oacc[nt][0] * inv0, oacc[nt][1] * inv0, hw, lw);
        g_attnH[((size_t)(bidx * S_ + r0)) * 512 + (col >> 1)] = hw;
        g_attnL[((size_t)(bidx * S_ + r0)) * 512 + (col >> 1)] = lw;
        split2(oacc[nt][2] * inv1, oacc[nt][3] * inv1, hw, lw);
        g_attnH[((size_t)(bidx * S_ + r0 + 8)) * 512 + (col >> 1)] = hw;
        g_attnL[((size_t)(bidx * S_ + r0 + 8)) * 512 + (col >> 1)] = lw;
    }
}

// ---------------------------------------------------------------------------
// Kernel 3: output projection, cp.async double-buffered, pre-packed operands.
// ---------------------------------------------------------------------------
__global__ __launch_bounds__(256) void proj_kernel(float* __restrict__ out)
{
    extern __shared__ unsigned sm[];
    const unsigned smemBase = (unsigned)__cvta_generic_to_shared(sm);

    const int bn = blockIdx.x * 128;
    const int bm = blockIdx.y * 128;

    const int tid  = threadIdx.x;
    const int lane = tid & 31;
    const int g    = lane >> 2;
    const int t    = lane & 3;
    const int wm   = (tid >> 5) >> 2;
    const int wn   = (tid >> 5) & 3;

    float acc[4][4][4];
    #pragma unroll
    for (int i = 0; i < 4; i++)
        #pragma unroll
        for (int j = 0; j < 4; j++)
            #pragma unroll
            for (int e = 0; e < 4; e++) acc[i][j][e] = 0.0f;

    gemm_ld_stage(smemBase, 0, tid, bm, bn, 0, g_attnH, g_attnL, g_WoH, g_WoL);
    CP_COMMIT();

    for (int it = 0; it < 32; it++) {
        const int buf = it & 1;
        if (it + 1 < 32) {
            gemm_ld_stage(smemBase, buf ^ 1, tid, bm, bn, (it + 1) * 16,
                          g_attnH, g_attnL, g_WoH, g_WoL);
            CP_COMMIT();
            asm volatile("cp.async.wait_group 1;");
        } else {
            asm volatile("cp.async.wait_group 0;");
        }
        __syncthreads();

        #pragma unroll
        for (int ks = 0; ks < 2; ks++) {
            const int kc = ks * 8 + t;
            unsigned aH[4][4], aL[4][4], bH[4][2], bL[4][2];
            #pragma unroll
            for (int mt = 0; mt < 4; mt++) {
                const int rb = wm * 64 + mt * 16;
                aH[mt][0] = sm[ASH_OFF + buf*2560 + (rb + g)     * 20 + kc];
                aH[mt][1] = sm[ASH_OFF + buf*2560 + (rb + 8 + g) * 20 + kc];
                aH[mt][2] = sm[ASH_OFF + buf*2560 + (rb + g)     * 20 + kc + 4];
                aH[mt][3] = sm[ASH_OFF + buf*2560 + (rb + 8 + g) * 20 + kc + 4];
                aL[mt][0] = sm[ASL_OFF + buf*2560 + (rb + g)     * 20 + kc];
                aL[mt][1] = sm[ASL_OFF + buf*2560 + (rb + 8 + g) * 20 + kc];
                aL[mt][2] = sm[ASL_OFF + buf*2560 + (rb + g)     * 20 + kc + 4];
                aL[mt][3] = sm[ASL_OFF + buf*2560 + (rb + 8 + g) * 20 + kc + 4];
            }
            #pragma unroll
            for (int nt = 0; nt < 4; nt++) {
                const int cb = wn * 32 + nt * 8 + g;
                bH[nt][0] = sm[BSH_OFF + buf*2112 + kc       * 132 + cb];
                bH[nt][1] = sm[BSH_OFF + buf*2112 + (kc + 4) * 132 + cb];
                bL[nt][0] = sm[BSL_OFF + buf*2112 + kc       * 132 + cb];
                bL[nt][1] = sm[BSL_OFF + buf*2112 + (kc + 4) * 132 + cb];
            }
            #pragma unroll
            for (int mt = 0; mt < 4; mt++)
                #pragma unroll
                for (int nt = 0; nt < 4; nt++) {
                    mma_bf16(acc[mt][nt], aH[mt], bH[nt]);
                    mma_bf16(acc[mt][nt], aH[mt], bL[nt]);
                    mma_bf16(acc[mt][nt], aL[mt], bH[nt]);
                }
        }
        __syncthreads();
    }

    #pragma unroll
    for (int mt = 0; mt < 4; mt++) {
        #pragma unroll
        for (int nt = 0; nt < 4; nt++) {
            const int col = bn + wn * 32 + nt * 8 + t * 2;
            #pragma unroll
            for (int half = 0; half < 2; half++) {
                const int row = bm + wm * 64 + mt * 16 + g + half * 8;
                float2 o = make_float2(acc[mt][nt][half * 2], acc[mt][nt][half * 2 + 1]);
                *(float2*)&out[(size_t)row * HID_ + col] = o;
            }
        }
    }
}

// ---------------------------------------------------------------------------
extern "C" void kernel_launch(void* const* d_in, const int* in_sizes, int n_in,
                              void* d_out, int out_size)
{
    const float* x    = (const float*)d_in[0];
    const float* sinu = (const float*)d_in[1];
    const float* bias = (const float*)d_in[2];
    const float* Wq   = (const float*)d_in[3];
    const float* bq   = (const float*)d_in[4];
    const float* Wk   = (const float*)d_in[5];
    const float* bk   = (const float*)d_in[6];
    const float* Wv   = (const float*)d_in[7];
    const float* bv   = (const float*)d_in[8];
    const float* Wo   = (const float*)d_in[9];
    float* out = (float*)d_out;

    cudaFuncSetAttribute(qkv_kernel,  cudaFuncAttributeMaxDynamicSharedMemorySize, GEMM_SMEM_BYTES);
    cudaFuncSetAttribute(proj_kernel, cudaFuncAttributeMaxDynamicSharedMemorySize, GEMM_SMEM_BYTES);

    prep_x<<<(BS_ * HID_ / 4) / 256, 256>>>(x);
    prep_w<<<512, 256>>>(Wq, 0);
    prep_w<<<512, 256>>>(Wk, 1);
    prep_w<<<512, 256>>>(Wv, 2);
    prep_w<<<512, 256>>>(Wo, 3);

    qkv_kernel<<<dim3(24, 32), 256, GEMM_SMEM_BYTES>>>(sinu, bq, bk, bv);
    attn_kernel<<<dim3(S_ / 128, H_, B_), 256>>>(bias);
    proj_kernel<<<dim3(8, 32), 256, GEMM_SMEM_BYTES>>>(out);
}

// round 6
// speedup vs baseline: 2.7039x; 1.1926x over previous
#include <cuda_runtime.h>
#include <cuda_bf16.h>

#define B_   2
#define S_   2048
#define H_   16
#define D_   64
#define HID_ 1024
#define ROT_ 32
#define BS_  (B_*S_)

// ---------------------------------------------------------------------------
// Device-global scratch (allocation-free rule)
// x, attn: bf16 [row][k] packed word=(k,k+1).  W: bf16 [k][n] packed word=(n,n+1).
// q,k: bf16 [b,h,s][d] packed word=(d,d+1).  v: f32 [b,h,s][d].
// ---------------------------------------------------------------------------
__device__ unsigned g_xH[(size_t)BS_*HID_/2], g_xL[(size_t)BS_*HID_/2];
__device__ unsigned g_WqH[HID_*HID_/2], g_WqL[HID_*HID_/2];
__device__ unsigned g_WkH[HID_*HID_/2], g_WkL[HID_*HID_/2];
__device__ unsigned g_WvH[HID_*HID_/2], g_WvL[HID_*HID_/2];
__device__ unsigned g_WoH[HID_*HID_/2], g_WoL[HID_*HID_/2];
__device__ unsigned g_qH[(size_t)B_*H_*S_*D_/2], g_qL[(size_t)B_*H_*S_*D_/2];
__device__ unsigned g_kH[(size_t)B_*H_*S_*D_/2], g_kL[(size_t)B_*H_*S_*D_/2];
__device__ float    g_v[(size_t)B_*H_*S_*D_];
__device__ unsigned g_attnH[(size_t)BS_*HID_/2], g_attnL[(size_t)BS_*HID_/2];

// ---------------------------------------------------------------------------
// bf16x3 + ldmatrix helpers
// ---------------------------------------------------------------------------
__device__ __forceinline__ unsigned pack_bf(__nv_bfloat16 a, __nv_bfloat16 b) {
    __nv_bfloat162 p; p.x = a; p.y = b;
    return *(unsigned*)&p;
}
__device__ __forceinline__ void split2(float x, float y, unsigned& hi, unsigned& lo) {
    __nv_bfloat16 hx = __float2bfloat16(x);
    __nv_bfloat16 hy = __float2bfloat16(y);
    __nv_bfloat16 lx = __float2bfloat16(x - __bfloat162float(hx));
    __nv_bfloat16 ly = __float2bfloat16(y - __bfloat162float(hy));
    hi = pack_bf(hx, hy);
    lo = pack_bf(lx, ly);
}
__device__ __forceinline__ void mma_bf16(float* d, const unsigned* a, const unsigned* b) {
    asm volatile(
        "mma.sync.aligned.m16n8k16.row.col.f32.bf16.bf16.f32 "
        "{%0,%1,%2,%3},{%4,%5,%6,%7},{%8,%9},{%0,%1,%2,%3};"
        : "+f"(d[0]), "+f"(d[1]), "+f"(d[2]), "+f"(d[3])
        : "r"(a[0]), "r"(a[1]), "r"(a[2]), "r"(a[3]), "r"(b[0]), "r"(b[1]));
}
__device__ __forceinline__ void ldsm4(unsigned* r, unsigned addr) {
    asm volatile("ldmatrix.sync.aligned.m8n8.x4.shared.b16 {%0,%1,%2,%3}, [%4];"
        : "=r"(r[0]), "=r"(r[1]), "=r"(r[2]), "=r"(r[3]) : "r"(addr));
}
__device__ __forceinline__ void ldsm4t(unsigned* r, unsigned addr) {
    asm volatile("ldmatrix.sync.aligned.m8n8.x4.trans.shared.b16 {%0,%1,%2,%3}, [%4];"
        : "=r"(r[0]), "=r"(r[1]), "=r"(r[2]), "=r"(r[3]) : "r"(addr));
}
__device__ __forceinline__ void cp16(unsigned saddr, const void* gptr) {
    asm volatile("cp.async.ca.shared.global [%0], [%1], 16;" :: "r"(saddr), "l"(gptr));
}
#define CP_COMMIT() asm volatile("cp.async.commit_group;")

// ---------------------------------------------------------------------------
// Prep kernels
// ---------------------------------------------------------------------------
__global__ void prep_x(const float* __restrict__ x) {
    const int i = blockIdx.x * 256 + threadIdx.x;        // float4 index
    float4 v = ((const float4*)x)[i];
    uint2 h, l;
    split2(v.x, v.y, h.x, l.x);
    split2(v.z, v.w, h.y, l.y);
    ((uint2*)g_xH)[i] = h;
    ((uint2*)g_xL)[i] = l;
}

// W stays [k][n]; just split into bf16 hi/lo words (pairs along n).
__global__ void prep_w(const float* __restrict__ W, int which) {
    unsigned* Hd = which == 0 ? g_WqH : which == 1 ? g_WkH : which == 2 ? g_WvH : g_WoH;
    unsigned* Ld = which == 0 ? g_WqL : which == 1 ? g_WkL : which == 2 ? g_WvL : g_WoL;
    const int j  = blockIdx.x * 256 + threadIdx.x;       // 0..262143
    const int k  = j >> 8;
    const int n4 = (j & 255) * 4;
    float4 a = *(const float4*)&W[(size_t)k * HID_ + n4];
    uint2 h, l;
    split2(a.x, a.y, h.x, l.x);
    split2(a.z, a.w, h.y, l.y);
    *(uint2*)&Hd[(size_t)k * 512 + (n4 >> 1)] = h;
    *(uint2*)&Ld[(size_t)k * 512 + (n4 >> 1)] = l;
}

// ---------------------------------------------------------------------------
// GEMM smem layout (words): AsH[2][128][20], AsL same; Bs bf16 [2][32][136]
// (=68 words/row).  Stage strides: A 2560 words, B 2176 words.
// ---------------------------------------------------------------------------
#define ASH_OFF 0
#define ASL_OFF 5120
#define BSH_OFF 10240
#define BSL_OFF 14592
#define GEMM_SMEM_BYTES (18944 * 4)    // 75776

__device__ __forceinline__ void gemm_ld_stage(
    unsigned smemBase, int s, int tid, int bm, int n0w, int ktw,
    const unsigned* __restrict__ AH, const unsigned* __restrict__ AL,
    const unsigned* __restrict__ WH, const unsigned* __restrict__ WL)
{
    #pragma unroll
    for (int p = 0; p < 2; p++) {
        const int c   = tid + p * 256;
        const int row = c >> 2;
        const int w4  = (c & 3) * 4;
        const size_t ga = (size_t)(bm + row) * 512 + ktw + w4;
        cp16(smemBase + (ASH_OFF + s * 2560 + row * 20 + w4) * 4, &AH[ga]);
        cp16(smemBase + (ASL_OFF + s * 2560 + row * 20 + w4) * 4, &AL[ga]);
        const int krow = c >> 4;
        const int w4b  = (c & 15) * 4;
        const size_t gb = (size_t)(2 * ktw + krow) * 512 + n0w + w4b;
        cp16(smemBase + (BSH_OFF + s * 2176 + krow * 68 + w4b) * 4, &WH[gb]);
        cp16(smemBase + (BSL_OFF + s * 2176 + krow * 68 + w4b) * 4, &WL[gb]);
    }
}

// Shared GEMM mainloop body: fragments via ldmatrix, 48 MMA per k16.
#define GEMM_MAINLOOP(AHsrc, ALsrc, WHsrc, WLsrc, N0W)                                  \
    gemm_ld_stage(smemBase, 0, tid, bm, N0W, 0, AHsrc, ALsrc, WHsrc, WLsrc);            \
    CP_COMMIT();                                                                        \
    for (int it = 0; it < 32; it++) {                                                   \
        const int buf = it & 1;                                                         \
        if (it + 1 < 32) {                                                              \
            gemm_ld_stage(smemBase, buf ^ 1, tid, bm, N0W, (it + 1) * 16,               \
                          AHsrc, ALsrc, WHsrc, WLsrc);                                  \
            CP_COMMIT();                                                                \
            asm volatile("cp.async.wait_group 1;");                                     \
        } else {                                                                        \
            asm volatile("cp.async.wait_group 0;");                                     \
        }                                                                               \
        __syncthreads();                                                                \
        _Pragma("unroll")                                                               \
        for (int ks = 0; ks < 2; ks++) {                                                \
            unsigned aH[4][4], aL[4][4], bH[4][2], bL[4][2];                            \
            const int arow = wm * 64 + (lane & 15);                                     \
            const int acol = ks * 8 + (lane >> 4) * 4;                                  \
            _Pragma("unroll")                                                           \
            for (int mt = 0; mt < 4; mt++) {                                            \
                ldsm4(aH[mt], smemBase + (ASH_OFF + buf * 2560 +                        \
                       (arow + mt * 16) * 20 + acol) * 4);                              \
                ldsm4(aL[mt], smemBase + (ASL_OFF + buf * 2560 +                        \
                       (arow + mt * 16) * 20 + acol) * 4);                              \
            }                                                                           \
            const int bkr = ks * 16 + (lane & 15);                                      \
            const int bnc = wn * 16 + (lane >> 4) * 4;                                  \
            _Pragma("unroll")                                                           \
            for (int np = 0; np < 2; np++) {                                            \
                unsigned r[4];                                                          \
                ldsm4t(r, smemBase + (BSH_OFF + buf * 2176 + bkr * 68 + bnc + np * 8) * 4); \
                bH[2*np][0] = r[0]; bH[2*np][1] = r[1];                                 \
                bH[2*np+1][0] = r[2]; bH[2*np+1][1] = r[3];                             \
                ldsm4t(r, smemBase + (BSL_OFF + buf * 2176 + bkr * 68 + bnc + np * 8) * 4); \
                bL[2*np][0] = r[0]; bL[2*np][1] = r[1];                                 \
                bL[2*np+1][0] = r[2]; bL[2*np+1][1] = r[3];                             \
            }                                                                           \
            _Pragma("unroll")                                                           \
            for (int mt = 0; mt < 4; mt++)                                              \
                _Pragma("unroll")                                                       \
                for (int nt = 0; nt < 4; nt++) {                                        \
                    mma_bf16(acc[mt][nt], aH[mt], bH[nt]);                              \
                    mma_bf16(acc[mt][nt], aH[mt], bL[nt]);                              \
                    mma_bf16(acc[mt][nt], aL[mt], bH[nt]);                              \
                }                                                                       \
        }                                                                               \
        __syncthreads();                                                                \
    }

// ---------------------------------------------------------------------------
// Kernel 1: fused QKV GEMM
// ---------------------------------------------------------------------------
__global__ __launch_bounds__(256) void qkv_kernel(
    const float* __restrict__ sinu,
    const float* __restrict__ bq, const float* __restrict__ bk,
    const float* __restrict__ bv)
{
    extern __shared__ unsigned sm[];
    const unsigned smemBase = (unsigned)__cvta_generic_to_shared(sm);

    const int bn  = blockIdx.x * 128;
    const int bm  = blockIdx.y * 128;
    const int mat = bn >> 10;
    const unsigned* __restrict__ WH = mat == 0 ? g_WqH : mat == 1 ? g_WkH : g_WvH;
    const unsigned* __restrict__ WL = mat == 0 ? g_WqL : mat == 1 ? g_WkL : g_WvL;
    const float*    __restrict__ bvec = mat == 0 ? bq : mat == 1 ? bk : bv;
    const int n0w = (bn & (HID_ - 1)) >> 1;

    const int tid  = threadIdx.x;
    const int lane = tid & 31;
    const int g    = lane >> 2;
    const int t    = lane & 3;
    const int wm   = (tid >> 5) >> 2;
    const int wn   = (tid >> 5) & 3;

    float acc[4][4][4];
    #pragma unroll
    for (int i = 0; i < 4; i++)
        #pragma unroll
        for (int j = 0; j < 4; j++)
            #pragma unroll
            for (int e = 0; e < 4; e++) acc[i][j][e] = 0.0f;

    GEMM_MAINLOOP(g_xH, g_xL, WH, WL, n0w)

    // epilogue: bias + rope + scale; pack q,k; f32 v.
    #pragma unroll
    for (int mt = 0; mt < 4; mt++) {
        #pragma unroll
        for (int nt = 0; nt < 4; nt++) {
            const int colg = bn + wn * 32 + nt * 8 + t * 2;
            const int cm   = colg & (HID_ - 1);
            const int hh   = cm >> 6;
            const int d0   = cm & 63;
            #pragma unroll
            for (int half = 0; half < 2; half++) {
                const int row  = bm + wm * 64 + mt * 16 + g + half * 8;
                const int bidx = row >> 11;
                const int s    = row & (S_ - 1);
                float v0 = acc[mt][nt][half * 2 + 0] + bvec[cm];
                float v1 = acc[mt][nt][half * 2 + 1] + bvec[cm + 1];
                if (mat < 2 && d0 < ROT_) {
                    const float sn0 = sinu[(((bidx * 2 + 0) * S_ + s) << 5) + d0];
                    const float cs0 = sinu[(((bidx * 2 + 1) * S_ + s) << 5) + d0];
                    const float sn1 = sinu[(((bidx * 2 + 0) * S_ + s) << 5) + d0 + 1];
                    const float cs1 = sinu[(((bidx * 2 + 1) * S_ + s) << 5) + d0 + 1];
                    v0 *= (cs0 - sn0);
                    v1 *= (cs1 + sn1);
                }
                const size_t base = ((size_t)bidx * H_ + hh) * S_ + s;
                if (mat == 2) {
                    *(float2*)&g_v[base * D_ + d0] = make_float2(v0, v1);
                } else {
                    if (mat == 0) { v0 *= 0.125f; v1 *= 0.125f; }
                    unsigned hw, lw;
                    split2(v0, v1, hw, lw);
                    if (mat == 0) {
                        g_qH[base * 32 + (d0 >> 1)] = hw;
                        g_qL[base * 32 + (d0 >> 1)] = lw;
                    } else {
                        g_kH[base * 32 + (d0 >> 1)] = hw;
                        g_kL[base * 32 + (d0 >> 1)] = lw;
                    }
                }
            }
        }
    }
}

// ---------------------------------------------------------------------------
// Kernel 2: flash attention.  256 thr, 128 q-rows/block, 32-key chunks.
// K via double-buffered cp.async; V register-pipelined into [key][d] rows;
// all fragments via ldmatrix.
// ---------------------------------------------------------------------------
__global__ __launch_bounds__(256) void attn_kernel(const float* __restrict__ bias)
{
    const int bidx = blockIdx.z;
    const int h    = blockIdx.y;
    const int q0   = blockIdx.x * 128;
    const int tid  = threadIdx.x;
    const int lane = tid & 31;
    const int g    = lane >> 2;
    const int t    = lane & 3;
    const int rb   = (tid >> 5) * 16;

    __shared__ unsigned KsH[2][32][36], KsL[2][32][36];   // [key][dword]
    __shared__ unsigned VsH[32][36],    VsL[32][36];      // [key][dword]
    __shared__ unsigned PsH[128][20],   PsL[128][20];     // [q][keyword]

    const unsigned ksHb = (unsigned)__cvta_generic_to_shared(&KsH[0][0][0]);
    const unsigned ksLb = (unsigned)__cvta_generic_to_shared(&KsL[0][0][0]);
    const unsigned vsHb = (unsigned)__cvta_generic_to_shared(&VsH[0][0]);
    const unsigned vsLb = (unsigned)__cvta_generic_to_shared(&VsL[0][0]);
    const unsigned psHb = (unsigned)__cvta_generic_to_shared(&PsH[0][0]);
    const unsigned psLb = (unsigned)__cvta_generic_to_shared(&PsL[0][0]);

    const size_t bh = (size_t)bidx * H_ + h;
    const unsigned* __restrict__ qHp = g_qH + (bh * S_ + q0) * 32;
    const unsigned* __restrict__ qLp = g_qL + (bh * S_ + q0) * 32;
    const unsigned* __restrict__ kHp = g_kH + bh * S_ * 32;
    const unsigned* __restrict__ kLp = g_kL + bh * S_ * 32;
    const float*    __restrict__ vbase = g_v + bh * S_ * D_;

    // Q fragments straight from packed gmem (register-resident)
    unsigned qaH[4][4], qaL[4][4];
    #pragma unroll
    for (int w = 0; w < 4; w++) {
        qaH[w][0] = qHp[(rb + g)     * 32 + w * 8 + t];
        qaH[w][1] = qHp[(rb + 8 + g) * 32 + w * 8 + t];
        qaH[w][2] = qHp[(rb + g)     * 32 + w * 8 + t + 4];
        qaH[w][3] = qHp[(rb + 8 + g) * 32 + w * 8 + t + 4];
        qaL[w][0] = qLp[(rb + g)     * 32 + w * 8 + t];
        qaL[w][1] = qLp[(rb + 8 + g) * 32 + w * 8 + t];
        qaL[w][2] = qLp[(rb + g)     * 32 + w * 8 + t + 4];
        qaL[w][3] = qLp[(rb + 8 + g) * 32 + w * 8 + t + 4];
    }

    float oacc[8][4];
    #pragma unroll
    for (int i = 0; i < 8; i++)
        #pragma unroll
        for (int e = 0; e < 4; e++) oacc[i][e] = 0.0f;
    float m0 = -1e30f, m1 = -1e30f, l0 = 0.0f, l1 = 0.0f;

    // loader indices
    const int krow = tid >> 3, kw4 = (tid & 7) * 4;   // K cp.async
    const int vrow = tid >> 3, vd8 = (tid & 7) * 8;   // V regs / store

    // fragment-lane offsets
    const int kfr = (lane & 7) + ((lane >> 4) & 1) * 8;   // K: key within np*16
    const int kfd = ((lane >> 3) & 1) * 4;                // K: dword half
    const int vfr = (lane & 7) + ((lane >> 3) & 1) * 8;   // V: key within w*16
    const int vfc = (lane >> 4) * 4;                      // V: dword within np*8
    const int pfr = rb + (lane & 15);                     // P: q row
    const int pfc = (lane >> 4) * 4;                      // P: keyword half

    // preload chunk 0
    cp16(ksHb + (krow * 36 + kw4) * 4, &kHp[(size_t)krow * 32 + kw4]);
    cp16(ksLb + (krow * 36 + kw4) * 4, &kLp[(size_t)krow * 32 + kw4]);
    CP_COMMIT();
    float4 vr0 = *(const float4*)&vbase[(size_t)vrow * D_ + vd8];
    float4 vr1 = *(const float4*)&vbase[(size_t)vrow * D_ + vd8 + 4];
    float2 bb0[4], bb1[4];
    {
        const size_t brow0 = ((size_t)bidx * S_ + (q0 + rb + g)) * S_;
        #pragma unroll
        for (int nt = 0; nt < 4; nt++) {
            bb0[nt] = *(const float2*)&bias[brow0 + nt * 8 + t * 2];
            bb1[nt] = *(const float2*)&bias[brow0 + (size_t)8 * S_ + nt * 8 + t * 2];
        }
    }

    for (int c = 0; c < 64; c++) {
        const int buf = c & 1;
        asm volatile("cp.async.wait_group 0;");
        __syncthreads();                      // K[c] landed; everyone done with Vs

        // store V chunk c (plain [key][d] bf16 rows)
        {
            uint4 hc, lc;
            split2(vr0.x, vr0.y, hc.x, lc.x);
            split2(vr0.z, vr0.w, hc.y, lc.y);
            split2(vr1.x, vr1.y, hc.z, lc.z);
            split2(vr1.z, vr1.w, hc.w, lc.w);
            *(uint4*)&VsH[vrow][vd8 >> 1] = hc;
            *(uint4*)&VsL[vrow][vd8 >> 1] = lc;
        }
        // issue next chunk
        if (c + 1 < 64) {
            const int kt2 = (c + 1) * 32;
            cp16(ksHb + ((buf ^ 1) * 1152 + krow * 36 + kw4) * 4,
                 &kHp[(size_t)(kt2 + krow) * 32 + kw4]);
            cp16(ksLb + ((buf ^ 1) * 1152 + krow * 36 + kw4) * 4,
                 &kLp[(size_t)(kt2 + krow) * 32 + kw4]);
            CP_COMMIT();
            vr0 = *(const float4*)&vbase[(size_t)(kt2 + vrow) * D_ + vd8];
            vr1 = *(const float4*)&vbase[(size_t)(kt2 + vrow) * D_ + vd8 + 4];
        }
        __syncthreads();                      // Vs visible

        // S = Q K^T : 16x32, K=64
        float sacc[4][4];
        #pragma unroll
        for (int nt = 0; nt < 4; nt++)
            #pragma unroll
            for (int e = 0; e < 4; e++) sacc[nt][e] = 0.0f;
        #pragma unroll
        for (int w = 0; w < 4; w++) {
            #pragma unroll
            for (int np = 0; np < 2; np++) {
                unsigned rH[4], rL[4];
                const unsigned off = (buf * 1152 + (np * 16 + kfr) * 36 + w * 8 + kfd) * 4;
                ldsm4(rH, ksHb + off);
                ldsm4(rL, ksLb + off);
                mma_bf16(sacc[2*np],   qaH[w], rH);
                mma_bf16(sacc[2*np],   qaH[w], rL);
                mma_bf16(sacc[2*np],   qaL[w], rH);
                mma_bf16(sacc[2*np+1], qaH[w], rH + 2);
                mma_bf16(sacc[2*np+1], qaH[w], rL + 2);
                mma_bf16(sacc[2*np+1], qaL[w], rH + 2);
            }
        }

        // + bias (prefetched)
        #pragma unroll
        for (int nt = 0; nt < 4; nt++) {
            sacc[nt][0] += bb0[nt].x; sacc[nt][1] += bb0[nt].y;
            sacc[nt][2] += bb1[nt].x; sacc[nt][3] += bb1[nt].y;
        }

        // online softmax
        float mx0 = -1e30f, mx1 = -1e30f;
        #pragma unroll
        for (int nt = 0; nt < 4; nt++) {
            mx0 = fmaxf(mx0, fmaxf(sacc[nt][0], sacc[nt][1]));
            mx1 = fmaxf(mx1, fmaxf(sacc[nt][2], sacc[nt][3]));
        }
        mx0 = fmaxf(mx0, __shfl_xor_sync(0xffffffffu, mx0, 1));
        mx0 = fmaxf(mx0, __shfl_xor_sync(0xffffffffu, mx0, 2));
        mx1 = fmaxf(mx1, __shfl_xor_sync(0xffffffffu, mx1, 1));
        mx1 = fmaxf(mx1, __shfl_xor_sync(0xffffffffu, mx1, 2));
        const float mi0 = fmaxf(m0, mx0), mi1 = fmaxf(m1, mx1);
        const float c0 = __expf(m0 - mi0), c1 = __expf(m1 - mi1);
        m0 = mi0; m1 = mi1;
        float rs0 = 0.0f, rs1 = 0.0f;
        #pragma unroll
        for (int nt = 0; nt < 4; nt++) {
            sacc[nt][0] = __expf(sacc[nt][0] - mi0);
            sacc[nt][1] = __expf(sacc[nt][1] - mi0);
            sacc[nt][2] = __expf(sacc[nt][2] - mi1);
            sacc[nt][3] = __expf(sacc[nt][3] - mi1);
            rs0 += sacc[nt][0] + sacc[nt][1];
            rs1 += sacc[nt][2] + sacc[nt][3];
        }
        rs0 += __shfl_xor_sync(0xffffffffu, rs0, 1);
        rs0 += __shfl_xor_sync(0xffffffffu, rs0, 2);
        rs1 += __shfl_xor_sync(0xffffffffu, rs1, 1);
        rs1 += __shfl_xor_sync(0xffffffffu, rs1, 2);
        l0 = l0 * c0 + rs0;
        l1 = l1 * c1 + rs1;
        #pragma unroll
        for (int nt = 0; nt < 8; nt++) {
            oacc[nt][0] *= c0; oacc[nt][1] *= c0;
            oacc[nt][2] *= c1; oacc[nt][3] *= c1;
        }

        // P -> smem (hi/lo, plain [q][key] rows, pairs along key)
        #pragma unroll
        for (int nt = 0; nt < 4; nt++) {
            unsigned hp, lp;
            split2(sacc[nt][0], sacc[nt][1], hp, lp);
            PsH[rb + g][nt * 4 + t] = hp;
            PsL[rb + g][nt * 4 + t] = lp;
            split2(sacc[nt][2], sacc[nt][3], hp, lp);
            PsH[rb + 8 + g][nt * 4 + t] = hp;
            PsL[rb + 8 + g][nt * 4 + t] = lp;
        }
        __syncwarp();

        // O += P V : 16x64, K=32
        #pragma unroll
        for (int w = 0; w < 2; w++) {
            unsigned paH[4], paL[4];
            ldsm4(paH, psHb + (pfr * 20 + w * 8 + pfc) * 4);
            ldsm4(paL, psLb + (pfr * 20 + w * 8 + pfc) * 4);
            #pragma unroll
            for (int np = 0; np < 4; np++) {
                unsigned rH[4], rL[4];
                const unsigned off = ((w * 16 + vfr) * 36 + np * 8 + vfc) * 4;
                ldsm4t(rH, vsHb + off);
                ldsm4t(rL, vsLb + off);
                mma_bf16(oacc[2*np],   paH, rH);
                mma_bf16(oacc[2*np],   paH, rL);
                mma_bf16(oacc[2*np],   paL, rH);
                mma_bf16(oacc[2*np+1], paH, rH + 2);
                mma_bf16(oacc[2*np+1], paH, rL + 2);
                mma_bf16(oacc[2*np+1], paL, rH + 2);
            }
        }

        // prefetch bias for next chunk
        if (c + 1 < 64) {
            const size_t brow0 = ((size_t)bidx * S_ + (q0 + rb + g)) * S_ + (c + 1) * 32;
            #pragma unroll
            for (int nt = 0; nt < 4; nt++) {
                bb0[nt] = *(const float2*)&bias[brow0 + nt * 8 + t * 2];
                bb1[nt] = *(const float2*)&bias[brow0 + (size_t)8 * S_ + nt * 8 + t * 2];
            }
        }
    }

    // normalize + write packed [B,S,HID] for proj
    const float inv0 = 1.0f / l0, inv1 = 1.0f / l1;
    #pragma unroll
    for (int nt = 0; nt < 8; nt++) {
        const int col = h * D_ + nt * 8 + t * 2;
        const int r0  = q0 + rb + g;
        unsigned hw, lw;
        split2(oacc[nt][0] * inv0, oacc[nt][1] * inv0, hw, lw);
        g_attnH[((size_t)(bidx * S_ + r0)) * 512 + (col >> 1)] = hw;
        g_attnL[((size_t)(bidx * S_ + r0)) * 512 + (col >> 1)] = lw;
        split2(oacc[nt][2] * inv1, oacc[nt][3] * inv1, hw, lw);
        g_attnH[((size_t)(bidx * S_ + r0 + 8)) * 512 + (col >> 1)] = hw;
        g_attnL[((size_t)(bidx * S_ + r0 + 8)) * 512 + (col >> 1)] = lw;
    }
}

// ---------------------------------------------------------------------------
// Kernel 3: output projection
// ---------------------------------------------------------------------------
__global__ __launch_bounds__(256) void proj_kernel(float* __restrict__ out)
{
    extern __shared__ unsigned sm[];
    const unsigned smemBase = (unsigned)__cvta_generic_to_shared(sm);

    const int bn = blockIdx.x * 128;
    const int bm = blockIdx.y * 128;
    const int n0w = bn >> 1;

    const int tid  = threadIdx.x;
    const int lane = tid & 31;
    const int g    = lane >> 2;
    const int t    = lane & 3;
    const int wm   = (tid >> 5) >> 2;
    const int wn   = (tid >> 5) & 3;

    float acc[4][4][4];
    #pragma unroll
    for (int i = 0; i < 4; i++)
        #pragma unroll
        for (int j = 0; j < 4; j++)
            #pragma unroll
            for (int e = 0; e < 4; e++) acc[i][j][e] = 0.0f;

    GEMM_MAINLOOP(g_attnH, g_attnL, g_WoH, g_WoL, n0w)

    #pragma unroll
    for (int mt = 0; mt < 4; mt++) {
        #pragma unroll
        for (int nt = 0; nt < 4; nt++) {
            const int col = bn + wn * 32 + nt * 8 + t * 2;
            #pragma unroll
            for (int half = 0; half < 2; half++) {
                const int row = bm + wm * 64 + mt * 16 + g + half * 8;
                float2 o = make_float2(acc[mt][nt][half * 2], acc[mt][nt][half * 2 + 1]);
                *(float2*)&out[(size_t)row * HID_ + col] = o;
            }
        }
    }
}

// ---------------------------------------------------------------------------
extern "C" void kernel_launch(void* const* d_in, const int* in_sizes, int n_in,
                              void* d_out, int out_size)
{
    const float* x    = (const float*)d_in[0];
    const float* sinu = (const float*)d_in[1];
    const float* bias = (const float*)d_in[2];
    const float* Wq   = (const float*)d_in[3];
    const float* bq   = (const float*)d_in[4];
    const float* Wk   = (const float*)d_in[5];
    const float* bk   = (const float*)d_in[6];
    const float* Wv   = (const float*)d_in[7];
    const float* bv   = (const float*)d_in[8];
    const float* Wo   = (const float*)d_in[9];
    float* out = (float*)d_out;

    cudaFuncSetAttribute(qkv_kernel,  cudaFuncAttributeMaxDynamicSharedMemorySize, GEMM_SMEM_BYTES);
    cudaFuncSetAttribute(proj_kernel, cudaFuncAttributeMaxDynamicSharedMemorySize, GEMM_SMEM_BYTES);

    prep_x<<<(BS_ * HID_ / 4) / 256, 256>>>(x);
    prep_w<<<1024, 256>>>(Wq, 0);
    prep_w<<<1024, 256>>>(Wk, 1);
    prep_w<<<1024, 256>>>(Wv, 2);
    prep_w<<<1024, 256>>>(Wo, 3);

    qkv_kernel<<<dim3(24, 32), 256, GEMM_SMEM_BYTES>>>(sinu, bq, bk, bv);
    attn_kernel<<<dim3(S_ / 128, H_, B_), 256>>>(bias);
    proj_kernel<<<dim3(8, 32), 256, GEMM_SMEM_BYTES>>>(out);
}

// round 8
// speedup vs baseline: 2.8232x; 1.0441x over previous
#include <cuda_runtime.h>
#include <cuda_bf16.h>

#define B_   2
#define S_   2048
#define H_   16
#define D_   64
#define HID_ 1024
#define ROT_ 32
#define BS_  (B_*S_)
#define LOG2E 1.44269504088896f

// ---------------------------------------------------------------------------
// Device-global scratch (allocation-free rule)
// ---------------------------------------------------------------------------
__device__ unsigned g_xH[(size_t)BS_*HID_/2], g_xL[(size_t)BS_*HID_/2];
__device__ unsigned g_WqH[HID_*HID_/2], g_WqL[HID_*HID_/2];
__device__ unsigned g_WkH[HID_*HID_/2], g_WkL[HID_*HID_/2];
__device__ unsigned g_WvH[HID_*HID_/2], g_WvL[HID_*HID_/2];
__device__ unsigned g_WoH[HID_*HID_/2], g_WoL[HID_*HID_/2];
__device__ unsigned g_qH[(size_t)B_*H_*S_*D_/2], g_qL[(size_t)B_*H_*S_*D_/2];
__device__ unsigned g_kH[(size_t)B_*H_*S_*D_/2], g_kL[(size_t)B_*H_*S_*D_/2];
__device__ float    g_v[(size_t)B_*H_*S_*D_];
__device__ unsigned g_attnH[(size_t)BS_*HID_/2], g_attnL[(size_t)BS_*HID_/2];

// ---------------------------------------------------------------------------
// helpers
// ---------------------------------------------------------------------------
__device__ __forceinline__ unsigned pack_bf(__nv_bfloat16 a, __nv_bfloat16 b) {
    __nv_bfloat162 p; p.x = a; p.y = b;
    return *(unsigned*)&p;
}
__device__ __forceinline__ void split2(float x, float y, unsigned& hi, unsigned& lo) {
    __nv_bfloat16 hx = __float2bfloat16(x);
    __nv_bfloat16 hy = __float2bfloat16(y);
    __nv_bfloat16 lx = __float2bfloat16(x - __bfloat162float(hx));
    __nv_bfloat16 ly = __float2bfloat16(y - __bfloat162float(hy));
    hi = pack_bf(hx, hy);
    lo = pack_bf(lx, ly);
}
__device__ __forceinline__ void mma_bf16(float* d, const unsigned* a, const unsigned* b) {
    asm volatile(
        "mma.sync.aligned.m16n8k16.row.col.f32.bf16.bf16.f32 "
        "{%0,%1,%2,%3},{%4,%5,%6,%7},{%8,%9},{%0,%1,%2,%3};"
        : "+f"(d[0]), "+f"(d[1]), "+f"(d[2]), "+f"(d[3])
        : "r"(a[0]), "r"(a[1]), "r"(a[2]), "r"(a[3]), "r"(b[0]), "r"(b[1]));
}
__device__ __forceinline__ void ldsm4(unsigned* r, unsigned addr) {
    asm volatile("ldmatrix.sync.aligned.m8n8.x4.shared.b16 {%0,%1,%2,%3}, [%4];"
        : "=r"(r[0]), "=r"(r[1]), "=r"(r[2]), "=r"(r[3]) : "r"(addr));
}
__device__ __forceinline__ void ldsm4t(unsigned* r, unsigned addr) {
    asm volatile("ldmatrix.sync.aligned.m8n8.x4.trans.shared.b16 {%0,%1,%2,%3}, [%4];"
        : "=r"(r[0]), "=r"(r[1]), "=r"(r[2]), "=r"(r[3]) : "r"(addr));
}
__device__ __forceinline__ void cp16(unsigned saddr, const void* gptr) {
    asm volatile("cp.async.ca.shared.global [%0], [%1], 16;" :: "r"(saddr), "l"(gptr));
}
#define CP_COMMIT() asm volatile("cp.async.commit_group;")
__device__ __forceinline__ float ex2(float x) {
    float r;
    asm("ex2.approx.ftz.f32 %0, %1;" : "=f"(r) : "f"(x));
    return r;
}

// ---------------------------------------------------------------------------
// Prep kernels
// ---------------------------------------------------------------------------
__global__ void prep_x(const float* __restrict__ x) {
    const int i = blockIdx.x * 256 + threadIdx.x;        // float4 index
    float4 v = ((const float4*)x)[i];
    uint2 h, l;
    split2(v.x, v.y, h.x, l.x);
    split2(v.z, v.w, h.y, l.y);
    ((uint2*)g_xH)[i] = h;
    ((uint2*)g_xL)[i] = l;
}

// All four W matrices in one launch (blockIdx.y selects matrix).
__global__ void prep_w4(const float* __restrict__ Wq, const float* __restrict__ Wk,
                        const float* __restrict__ Wv, const float* __restrict__ Wo) {
    const int which = blockIdx.y;
    const float* W = which == 0 ? Wq : which == 1 ? Wk : which == 2 ? Wv : Wo;
    unsigned* Hd = which == 0 ? g_WqH : which == 1 ? g_WkH : which == 2 ? g_WvH : g_WoH;
    unsigned* Ld = which == 0 ? g_WqL : which == 1 ? g_WkL : which == 2 ? g_WvL : g_WoL;
    const int j  = blockIdx.x * 256 + threadIdx.x;       // 0..262143
    const int k  = j >> 8;
    const int n4 = (j & 255) * 4;
    float4 a = *(const float4*)&W[(size_t)k * HID_ + n4];
    uint2 h, l;
    split2(a.x, a.y, h.x, l.x);
    split2(a.z, a.w, h.y, l.y);
    *(uint2*)&Hd[(size_t)k * 512 + (n4 >> 1)] = h;
    *(uint2*)&Ld[(size_t)k * 512 + (n4 >> 1)] = l;
}

// ---------------------------------------------------------------------------
// GEMM smem layout (unchanged from round 6)
// ---------------------------------------------------------------------------
#define ASH_OFF 0
#define ASL_OFF 5120
#define BSH_OFF 10240
#define BSL_OFF 14592
#define GEMM_SMEM_BYTES (18944 * 4)    // 75776

__device__ __forceinline__ void gemm_ld_stage(
    unsigned smemBase, int s, int tid, int bm, int n0w, int ktw,
    const unsigned* __restrict__ AH, const unsigned* __restrict__ AL,
    const unsigned* __restrict__ WH, const unsigned* __restrict__ WL)
{
    #pragma unroll
    for (int p = 0; p < 2; p++) {
        const int c   = tid + p * 256;
        const int row = c >> 2;
        const int w4  = (c & 3) * 4;
        const size_t ga = (size_t)(bm + row) * 512 + ktw + w4;
        cp16(smemBase + (ASH_OFF + s * 2560 + row * 20 + w4) * 4, &AH[ga]);
        cp16(smemBase + (ASL_OFF + s * 2560 + row * 20 + w4) * 4, &AL[ga]);
        const int krow = c >> 4;
        const int w4b  = (c & 15) * 4;
        const size_t gb = (size_t)(2 * ktw + krow) * 512 + n0w + w4b;
        cp16(smemBase + (BSH_OFF + s * 2176 + krow * 68 + w4b) * 4, &WH[gb]);
        cp16(smemBase + (BSL_OFF + s * 2176 + krow * 68 + w4b) * 4, &WL[gb]);
    }
}

#define GEMM_MAINLOOP(AHsrc, ALsrc, WHsrc, WLsrc, N0W)                                  \
    gemm_ld_stage(smemBase, 0, tid, bm, N0W, 0, AHsrc, ALsrc, WHsrc, WLsrc);            \
    CP_COMMIT();                                                                        \
    for (int it = 0; it < 32; it++) {                                                   \
        const int buf = it & 1;                                                         \
        if (it + 1 < 32) {                                                              \
            gemm_ld_stage(smemBase, buf ^ 1, tid, bm, N0W, (it + 1) * 16,               \
                          AHsrc, ALsrc, WHsrc, WLsrc);                                  \
            CP_COMMIT();                                                                \
            asm volatile("cp.async.wait_group 1;");                                     \
        } else {                                                                        \
            asm volatile("cp.async.wait_group 0;");                                     \
        }                                                                               \
        __syncthreads();                                                                \
        _Pragma("unroll")                                                               \
        for (int ks = 0; ks < 2; ks++) {                                                \
            unsigned aH[4][4], aL[4][4], bH[4][2], bL[4][2];                            \
            const int arow = wm * 64 + (lane & 15);                                     \
            const int acol = ks * 8 + (lane >> 4) * 4;                                  \
            _Pragma("unroll")                                                           \
            for (int mt = 0; mt < 4; mt++) {                                            \
                ldsm4(aH[mt], smemBase + (ASH_OFF + buf * 2560 +                        \
                       (arow + mt * 16) * 20 + acol) * 4);                              \
                ldsm4(aL[mt], smemBase + (ASL_OFF + buf * 2560 +                        \
                       (arow + mt * 16) * 20 + acol) * 4);                              \
            }                                                                           \
            const int bkr = ks * 16 + (lane & 15);                                      \
            const int bnc = wn * 16 + (lane >> 4) * 4;                                  \
            _Pragma("unroll")                                                           \
            for (int np = 0; np < 2; np++) {                                            \
                unsigned r[4];                                                          \
                ldsm4t(r, smemBase + (BSH_OFF + buf * 2176 + bkr * 68 + bnc + np * 8) * 4); \
                bH[2*np][0] = r[0]; bH[2*np][1] = r[1];                                 \
                bH[2*np+1][0] = r[2]; bH[2*np+1][1] = r[3];                             \
                ldsm4t(r, smemBase + (BSL_OFF + buf * 2176 + bkr * 68 + bnc + np * 8) * 4); \
                bL[2*np][0] = r[0]; bL[2*np][1] = r[1];                                 \
                bL[2*np+1][0] = r[2]; bL[2*np+1][1] = r[3];                             \
            }                                                                           \
            _Pragma("unroll")                                                           \
            for (int mt = 0; mt < 4; mt++)                                              \
                _Pragma("unroll")                                                       \
                for (int nt = 0; nt < 4; nt++) {                                        \
                    mma_bf16(acc[mt][nt], aH[mt], bH[nt]);                              \
                    mma_bf16(acc[mt][nt], aH[mt], bL[nt]);                              \
                    mma_bf16(acc[mt][nt], aL[mt], bH[nt]);                              \
                }                                                                       \
        }                                                                               \
        __syncthreads();                                                                \
    }

// ---------------------------------------------------------------------------
// Kernel 1: fused QKV GEMM (unchanged except q scale folds log2e)
// ---------------------------------------------------------------------------
__global__ __launch_bounds__(256) void qkv_kernel(
    const float* __restrict__ sinu,
    const float* __restrict__ bq, const float* __restrict__ bk,
    const float* __restrict__ bv)
{
    extern __shared__ unsigned sm[];
    const unsigned smemBase = (unsigned)__cvta_generic_to_shared(sm);

    const int bn  = blockIdx.x * 128;
    const int bm  = blockIdx.y * 128;
    const int mat = bn >> 10;
    const unsigned* __restrict__ WH = mat == 0 ? g_WqH : mat == 1 ? g_WkH : g_WvH;
    const unsigned* __restrict__ WL = mat == 0 ? g_WqL : mat == 1 ? g_WkL : g_WvL;
    const float*    __restrict__ bvec = mat == 0 ? bq : mat == 1 ? bk : bv;
    const int n0w = (bn & (HID_ - 1)) >> 1;

    const int tid  = threadIdx.x;
    const int lane = tid & 31;
    const int g    = lane >> 2;
    const int t    = lane & 3;
    const int wm   = (tid >> 5) >> 2;
    const int wn   = (tid >> 5) & 3;

    float acc[4][4][4];
    #pragma unroll
    for (int i = 0; i < 4; i++)
        #pragma unroll
        for (int j = 0; j < 4; j++)
            #pragma unroll
            for (int e = 0; e < 4; e++) acc[i][j][e] = 0.0f;

    GEMM_MAINLOOP(g_xH, g_xL, WH, WL, n0w)

    #pragma unroll
    for (int mt = 0; mt < 4; mt++) {
        #pragma unroll
        for (int nt = 0; nt < 4; nt++) {
            const int colg = bn + wn * 32 + nt * 8 + t * 2;
            const int cm   = colg & (HID_ - 1);
            const int hh   = cm >> 6;
            const int d0   = cm & 63;
            #pragma unroll
            for (int half = 0; half < 2; half++) {
                const int row  = bm + wm * 64 + mt * 16 + g + half * 8;
                const int bidx = row >> 11;
                const int s    = row & (S_ - 1);
                float v0 = acc[mt][nt][half * 2 + 0] + bvec[cm];
                float v1 = acc[mt][nt][half * 2 + 1] + bvec[cm + 1];
                if (mat < 2 && d0 < ROT_) {
                    const float sn0 = sinu[(((bidx * 2 + 0) * S_ + s) << 5) + d0];
                    const float cs0 = sinu[(((bidx * 2 + 1) * S_ + s) << 5) + d0];
                    const float sn1 = sinu[(((bidx * 2 + 0) * S_ + s) << 5) + d0 + 1];
                    const float cs1 = sinu[(((bidx * 2 + 1) * S_ + s) << 5) + d0 + 1];
                    v0 *= (cs0 - sn0);
                    v1 *= (cs1 + sn1);
                }
                const size_t base = ((size_t)bidx * H_ + hh) * S_ + s;
                if (mat == 2) {
                    *(float2*)&g_v[base * D_ + d0] = make_float2(v0, v1);
                } else {
                    if (mat == 0) { v0 *= 0.125f * LOG2E; v1 *= 0.125f * LOG2E; }
                    unsigned hw, lw;
                    split2(v0, v1, hw, lw);
                    if (mat == 0) {
                        g_qH[base * 32 + (d0 >> 1)] = hw;
                        g_qL[base * 32 + (d0 >> 1)] = lw;
                    } else {
                        g_kH[base * 32 + (d0 >> 1)] = hw;
                        g_kL[base * 32 + (d0 >> 1)] = lw;
                    }
                }
            }
        }
    }
}

// ---------------------------------------------------------------------------
// Kernel 2: flash attention, 64-key chunks, dynamic smem (~90KB).
// Softmax in log2 domain (q pre-scaled by log2e; bias scaled at load).
// ---------------------------------------------------------------------------
#define KSH_OFF 0            // [2][64][36]
#define KSL_OFF 4608
#define VSH_OFF 9216         // [64][36]
#define VSL_OFF 11520
#define PSH_OFF 13824        // [128][36]
#define PSL_OFF 18432
#define ATTN_SMEM_BYTES (23040 * 4)   // 92160

__global__ __launch_bounds__(256) void attn_kernel(const float* __restrict__ bias)
{
    extern __shared__ unsigned sm[];
    const unsigned smemBase = (unsigned)__cvta_generic_to_shared(sm);

    const int bidx = blockIdx.z;
    const int h    = blockIdx.y;
    const int q0   = blockIdx.x * 128;
    const int tid  = threadIdx.x;
    const int lane = tid & 31;
    const int g    = lane >> 2;
    const int t    = lane & 3;
    const int rb   = (tid >> 5) * 16;

    const size_t bh = (size_t)bidx * H_ + h;
    const unsigned* __restrict__ qHp = g_qH + (bh * S_ + q0) * 32;
    const unsigned* __restrict__ qLp = g_qL + (bh * S_ + q0) * 32;
    const unsigned* __restrict__ kHp = g_kH + bh * S_ * 32;
    const unsigned* __restrict__ kLp = g_kL + bh * S_ * 32;
    const float*    __restrict__ vbase = g_v + bh * S_ * D_;

    // Q fragments, register-resident
    unsigned qaH[4][4], qaL[4][4];
    #pragma unroll
    for (int w = 0; w < 4; w++) {
        qaH[w][0] = qHp[(rb + g)     * 32 + w * 8 + t];
        qaH[w][1] = qHp[(rb + 8 + g) * 32 + w * 8 + t];
        qaH[w][2] = qHp[(rb + g)     * 32 + w * 8 + t + 4];
        qaH[w][3] = qHp[(rb + 8 + g) * 32 + w * 8 + t + 4];
        qaL[w][0] = qLp[(rb + g)     * 32 + w * 8 + t];
        qaL[w][1] = qLp[(rb + 8 + g) * 32 + w * 8 + t];
        qaL[w][2] = qLp[(rb + g)     * 32 + w * 8 + t + 4];
        qaL[w][3] = qLp[(rb + 8 + g) * 32 + w * 8 + t + 4];
    }

    float oacc[8][4];
    #pragma unroll
    for (int i = 0; i < 8; i++)
        #pragma unroll
        for (int e = 0; e < 4; e++) oacc[i][e] = 0.0f;
    float m0 = -1e30f, m1 = -1e30f, l0 = 0.0f, l1 = 0.0f;

    // loader indices (64 keys per chunk)
    const int krow = tid >> 3, kw4 = (tid & 7) * 4;   // K: 2 passes of 32 rows
    const int vrow = tid >> 2, vc  = (tid & 3) * 16;  // V: 1 row-quarter / thread

    // fragment-lane offsets
    const int kfr = (lane & 7) + ((lane >> 4) & 1) * 8;
    const int kfd = ((lane >> 3) & 1) * 4;
    const int vfr = (lane & 7) + ((lane >> 3) & 1) * 8;
    const int vfc = (lane >> 4) * 4;
    const int pfr = rb + (lane & 15);
    const int pfc = (lane >> 4) * 4;

    // preload chunk 0
    #pragma unroll
    for (int p = 0; p < 2; p++) {
        const int r = krow + p * 32;
        cp16(smemBase + (KSH_OFF + r * 36 + kw4) * 4, &kHp[(size_t)r * 32 + kw4]);
        cp16(smemBase + (KSL_OFF + r * 36 + kw4) * 4, &kLp[(size_t)r * 32 + kw4]);
    }
    CP_COMMIT();
    float4 vr[4];
    #pragma unroll
    for (int j = 0; j < 4; j++)
        vr[j] = *(const float4*)&vbase[(size_t)vrow * D_ + vc + j * 4];

    const size_t brow0 = ((size_t)bidx * S_ + (q0 + rb + g)) * S_;
    const size_t brow1 = brow0 + (size_t)8 * S_;

    for (int c = 0; c < 32; c++) {
        const int buf = c & 1;
        asm volatile("cp.async.wait_group 0;");
        __syncthreads();                  // K[c] landed; all warps done with Vs/Ps

        // bias for this chunk (issue early; consumed after S-GEMM)
        float2 bb0[8], bb1[8];
        #pragma unroll
        for (int nt = 0; nt < 8; nt++) {
            bb0[nt] = *(const float2*)&bias[brow0 + c * 64 + nt * 8 + t * 2];
            bb1[nt] = *(const float2*)&bias[brow1 + c * 64 + nt * 8 + t * 2];
        }

        // store V chunk c (bf16 [key][d] rows)
        #pragma unroll
        for (int j = 0; j < 4; j++) {
            uint2 hc, lc;
            split2(vr[j].x, vr[j].y, hc.x, lc.x);
            split2(vr[j].z, vr[j].w, hc.y, lc.y);
            *(uint2*)&sm[VSH_OFF + vrow * 36 + (vc >> 1) + j * 2] = hc;
            *(uint2*)&sm[VSL_OFF + vrow * 36 + (vc >> 1) + j * 2] = lc;
        }
        // issue next chunk
        if (c + 1 < 32) {
            const int kt2 = (c + 1) * 64;
            #pragma unroll
            for (int p = 0; p < 2; p++) {
                const int r = krow + p * 32;
                cp16(smemBase + (KSH_OFF + (buf ^ 1) * 2304 + r * 36 + kw4) * 4,
                     &kHp[(size_t)(kt2 + r) * 32 + kw4]);
                cp16(smemBase + (KSL_OFF + (buf ^ 1) * 2304 + r * 36 + kw4) * 4,
                     &kLp[(size_t)(kt2 + r) * 32 + kw4]);
            }
            CP_COMMIT();
            #pragma unroll
            for (int j = 0; j < 4; j++)
                vr[j] = *(const float4*)&vbase[(size_t)(kt2 + vrow) * D_ + vc + j * 4];
        }
        __syncthreads();                  // Vs visible

        // S = Q K^T : 16x64, K=64
        float sacc[8][4];
        #pragma unroll
        for (int nt = 0; nt < 8; nt++)
            #pragma unroll
            for (int e = 0; e < 4; e++) sacc[nt][e] = 0.0f;
        #pragma unroll
        for (int w = 0; w < 4; w++) {
            #pragma unroll
            for (int np = 0; np < 4; np++) {
                unsigned rH[4], rL[4];
                const unsigned off = (KSH_OFF + buf * 2304 + (np * 16 + kfr) * 36 + w * 8 + kfd) * 4;
                ldsm4(rH, smemBase + off);
                ldsm4(rL, smemBase + off + (KSL_OFF - KSH_OFF) * 4);
                mma_bf16(sacc[2*np],   qaH[w], rH);
                mma_bf16(sacc[2*np],   qaH[w], rL);
                mma_bf16(sacc[2*np],   qaL[w], rH);
                mma_bf16(sacc[2*np+1], qaH[w], rH + 2);
                mma_bf16(sacc[2*np+1], qaH[w], rL + 2);
                mma_bf16(sacc[2*np+1], qaL[w], rH + 2);
            }
        }

        // + bias (log2 domain)
        #pragma unroll
        for (int nt = 0; nt < 8; nt++) {
            sacc[nt][0] += LOG2E * bb0[nt].x; sacc[nt][1] += LOG2E * bb0[nt].y;
            sacc[nt][2] += LOG2E * bb1[nt].x; sacc[nt][3] += LOG2E * bb1[nt].y;
        }

        // online softmax (base-2)
        float mx0 = -1e30f, mx1 = -1e30f;
        #pragma unroll
        for (int nt = 0; nt < 8; nt++) {
            mx0 = fmaxf(mx0, fmaxf(sacc[nt][0], sacc[nt][1]));
            mx1 = fmaxf(mx1, fmaxf(sacc[nt][2], sacc[nt][3]));
        }
        mx0 = fmaxf(mx0, __shfl_xor_sync(0xffffffffu, mx0, 1));
        mx0 = fmaxf(mx0, __shfl_xor_sync(0xffffffffu, mx0, 2));
        mx1 = fmaxf(mx1, __shfl_xor_sync(0xffffffffu, mx1, 1));
        mx1 = fmaxf(mx1, __shfl_xor_sync(0xffffffffu, mx1, 2));
        const float mi0 = fmaxf(m0, mx0), mi1 = fmaxf(m1, mx1);
        const float c0 = ex2(m0 - mi0), c1 = ex2(m1 - mi1);
        m0 = mi0; m1 = mi1;
        float rs0 = 0.0f, rs1 = 0.0f;
        #pragma unroll
        for (int nt = 0; nt < 8; nt++) {
            sacc[nt][0] = ex2(sacc[nt][0] - mi0);
            sacc[nt][1] = ex2(sacc[nt][1] - mi0);
            sacc[nt][2] = ex2(sacc[nt][2] - mi1);
            sacc[nt][3] = ex2(sacc[nt][3] - mi1);
            rs0 += sacc[nt][0] + sacc[nt][1];
            rs1 += sacc[nt][2] + sacc[nt][3];
        }
        rs0 += __shfl_xor_sync(0xffffffffu, rs0, 1);
        rs0 += __shfl_xor_sync(0xffffffffu, rs0, 2);
        rs1 += __shfl_xor_sync(0xffffffffu, rs1, 1);
        rs1 += __shfl_xor_sync(0xffffffffu, rs1, 2);
        l0 = l0 * c0 + rs0;
        l1 = l1 * c1 + rs1;
        #pragma unroll
        for (int nt = 0; nt < 8; nt++) {
            oacc[nt][0] *= c0; oacc[nt][1] *= c0;
            oacc[nt][2] *= c1; oacc[nt][3] *= c1;
        }

        // P -> smem (hi/lo, pairs along key: word = (key,key+1))
        #pragma unroll
        for (int nt = 0; nt < 8; nt++) {
            unsigned hp, lp;
            split2(sacc[nt][0], sacc[nt][1], hp, lp);
            sm[PSH_OFF + (rb + g) * 36 + nt * 4 + t] = hp;
            sm[PSL_OFF + (rb + g) * 36 + nt * 4 + t] = lp;
            split2(sacc[nt][2], sacc[nt][3], hp, lp);
            sm[PSH_OFF + (rb + 8 + g) * 36 + nt * 4 + t] = hp;
            sm[PSL_OFF + (rb + 8 + g) * 36 + nt * 4 + t] = lp;
        }
        __syncwarp();

        // O += P V : 16x64, K=64
        #pragma unroll
        for (int w = 0; w < 4; w++) {
            unsigned paH[4], paL[4];
            ldsm4(paH, smemBase + (PSH_OFF + pfr * 36 + w * 8 + pfc) * 4);
            ldsm4(paL, smemBase + (PSL_OFF + pfr * 36 + w * 8 + pfc) * 4);
            #pragma unroll
            for (int np = 0; np < 4; np++) {
                unsigned rH[4], rL[4];
                const unsigned off = (VSH_OFF + (w * 16 + vfr) * 36 + np * 8 + vfc) * 4;
                ldsm4t(rH, smemBase + off);
                ldsm4t(rL, smemBase + off + (VSL_OFF - VSH_OFF) * 4);
                mma_bf16(oacc[2*np],   paH, rH);
                mma_bf16(oacc[2*np],   paH, rL);
                mma_bf16(oacc[2*np],   paL, rH);
                mma_bf16(oacc[2*np+1], paH, rH + 2);
                mma_bf16(oacc[2*np+1], paH, rL + 2);
                mma_bf16(oacc[2*np+1], paL, rH + 2);
            }
        }
    }

    // normalize + write packed [B,S,HID] for proj
    const float inv0 = 1.0f / l0, inv1 = 1.0f / l1;
    #pragma unroll
    for (int nt = 0; nt < 8; nt++) {
        const int col = h * D_ + nt * 8 + t * 2;
        const int r0  = q0 + rb + g;
        unsigned hw, lw;
        split2(oacc[nt][0] * inv0, oacc[nt][1] * inv0, hw, lw);
        g_attnH[((size_t)(bidx * S_ + r0)) * 512 + (col >> 1)] = hw;
        g_attnL[((size_t)(bidx * S_ + r0)) * 512 + (col >> 1)] = lw;
        split2(oacc[nt][2] * inv1, oacc[nt][3] * inv1, hw, lw);
        g_attnH[((size_t)(bidx * S_ + r0 + 8)) * 512 + (col >> 1)] = hw;
        g_attnL[((size_t)(bidx * S_ + r0 + 8)) * 512 + (col >> 1)] = lw;
    }
}

// ---------------------------------------------------------------------------
// Kernel 3: output projection (unchanged)
// ---------------------------------------------------------------------------
__global__ __launch_bounds__(256) void proj_kernel(float* __restrict__ out)
{
    extern __shared__ unsigned sm[];
    const unsigned smemBase = (unsigned)__cvta_generic_to_shared(sm);

    const int bn = blockIdx.x * 128;
    const int bm = blockIdx.y * 128;
    const int n0w = bn >> 1;

    const int tid  = threadIdx.x;
    const int lane = tid & 31;
    const int g    = lane >> 2;
    const int t    = lane & 3;
    const int wm   = (tid >> 5) >> 2;
    const int wn   = (tid >> 5) & 3;

    float acc[4][4][4];
    #pragma unroll
    for (int i = 0; i < 4; i++)
        #pragma unroll
        for (int j = 0; j < 4; j++)
            #pragma unroll
            for (int e = 0; e < 4; e++) acc[i][j][e] = 0.0f;

    GEMM_MAINLOOP(g_attnH, g_attnL, g_WoH, g_WoL, n0w)

    #pragma unroll
    for (int mt = 0; mt < 4; mt++) {
        #pragma unroll
        for (int nt = 0; nt < 4; nt++) {
            const int col = bn + wn * 32 + nt * 8 + t * 2;
            #pragma unroll
            for (int half = 0; half < 2; half++) {
                const int row = bm + wm * 64 + mt * 16 + g + half * 8;
                float2 o = make_float2(acc[mt][nt][half * 2], acc[mt][nt][half * 2 + 1]);
                *(float2*)&out[(size_t)row * HID_ + col] = o;
            }
        }
    }
}

// ---------------------------------------------------------------------------
extern "C" void kernel_launch(void* const* d_in, const int* in_sizes, int n_in,
                              void* d_out, int out_size)
{
    const float* x    = (const float*)d_in[0];
    const float* sinu = (const float*)d_in[1];
    const float* bias = (const float*)d_in[2];
    const float* Wq   = (const float*)d_in[3];
    const float* bq   = (const float*)d_in[4];
    const float* Wk   = (const float*)d_in[5];
    const float* bk   = (const float*)d_in[6];
    const float* Wv   = (const float*)d_in[7];
    const float* bv   = (const float*)d_in[8];
    const float* Wo   = (const float*)d_in[9];
    float* out = (float*)d_out;

    cudaFuncSetAttribute(qkv_kernel,  cudaFuncAttributeMaxDynamicSharedMemorySize, GEMM_SMEM_BYTES);
    cudaFuncSetAttribute(attn_kernel, cudaFuncAttributeMaxDynamicSharedMemorySize, ATTN_SMEM_BYTES);
    cudaFuncSetAttribute(proj_kernel, cudaFuncAttributeMaxDynamicSharedMemorySize, GEMM_SMEM_BYTES);

    prep_x<<<(BS_ * HID_ / 4) / 256, 256>>>(x);
    prep_w4<<<dim3(1024, 4), 256>>>(Wq, Wk, Wv, Wo);

    qkv_kernel<<<dim3(24, 32), 256, GEMM_SMEM_BYTES>>>(sinu, bq, bk, bv);
    attn_kernel<<<dim3(S_ / 128, H_, B_), 256, ATTN_SMEM_BYTES>>>(bias);
    proj_kernel<<<dim3(8, 32), 256, GEMM_SMEM_BYTES>>>(out);
}